// round 12
// baseline (speedup 1.0000x reference)
#include <cuda_runtime.h>
#include <cuda_fp16.h>
#include <cstdint>

#define NN 50000
#define NE 1600000
#define ESZ (NE + 8 * NN)   // padded edge capacity

// ---------------- scratch (static device globals; no allocs allowed) ----------------
__device__ __half g_h16[(NN + 1) * 128]; // gather source / y (+ zero row)
__device__ __half g_z16[NN * 128];       // agg output / GEMM input
__device__ __half g_t16[NN * 128];       // MLP intermediate
__device__ __half g_x16[(NN + 1) * 19];  // fp16 input (+ zero row)
__device__ float  g_vm[64];
__device__ float  g_vd[64];
__device__ float  g_sc[2];
__device__ float  g_td[NN + 1];
__device__ int    g_rowp[NN + 1];
__device__ int    g_cnt[NN];
__device__ int    g_cur[NN];
__device__ int    g_part[NN];
__device__ int    g_bsum[256];
__device__ int    g_esrc[ESZ];

// ---------------- CSR build ----------------
__global__ void count_k(const int* __restrict__ dst, int* __restrict__ cnt, int E) {
    int base = (blockIdx.x * blockDim.x + threadIdx.x) * 4;
    if (base + 4 <= E) {
        int4 d = *(const int4*)(dst + base);
        atomicAdd(&cnt[d.x], 1);
        atomicAdd(&cnt[d.y], 1);
        atomicAdd(&cnt[d.z], 1);
        atomicAdd(&cnt[d.w], 1);
    } else {
        for (int e = base; e < E; ++e) atomicAdd(&cnt[dst[e]], 1);
    }
}

// inclusive scan of PADDED counts (rounded up to multiple of 8)
__global__ void block_scan_k(const int* __restrict__ cnt, int* __restrict__ part,
                             int* __restrict__ bsum, int n) {
    __shared__ int wsum[8];
    int t = threadIdx.x;
    int i = blockIdx.x * 256 + t;
    int v = (i < n) ? ((cnt[i] + 7) & ~7) : 0;
    int lane = t & 31, w = t >> 5;
    int x = v;
#pragma unroll
    for (int o = 1; o < 32; o <<= 1) {
        int y = __shfl_up_sync(0xffffffffu, x, o);
        if (lane >= o) x += y;
    }
    if (lane == 31) wsum[w] = x;
    __syncthreads();
    if (w == 0) {
        int s = (lane < 8) ? wsum[lane] : 0;
#pragma unroll
        for (int o = 1; o < 8; o <<= 1) {
            int y = __shfl_up_sync(0xffffffffu, s, o);
            if (lane >= o) s += y;
        }
        if (lane < 8) wsum[lane] = s;
    }
    __syncthreads();
    if (w > 0) x += wsum[w - 1];
    if (i < n) part[i] = x;
    if (t == 255) bsum[blockIdx.x] = x;
}

__global__ void scan_bsum_k(int* __restrict__ bsum, int nb) {
    __shared__ int wsum[8];
    int t = threadIdx.x;
    int v = (t < nb) ? bsum[t] : 0;
    int lane = t & 31, w = t >> 5;
    int x = v;
#pragma unroll
    for (int o = 1; o < 32; o <<= 1) {
        int y = __shfl_up_sync(0xffffffffu, x, o);
        if (lane >= o) x += y;
    }
    if (lane == 31) wsum[w] = x;
    __syncthreads();
    if (w == 0) {
        int s = (lane < 8) ? wsum[lane] : 0;
#pragma unroll
        for (int o = 1; o < 8; o <<= 1) {
            int y = __shfl_up_sync(0xffffffffu, s, o);
            if (lane >= o) s += y;
        }
        if (lane < 8) wsum[lane] = s;
    }
    __syncthreads();
    if (w > 0) x += wsum[w - 1];
    if (t < nb) bsum[t] = x - v;   // exclusive
}

// rowp[i+1] = padded inclusive scan; cursor[i] = padded exclusive scan (= rowp[i]).
__global__ void finalize_rowp_k(const int* __restrict__ part, const int* __restrict__ bsum,
                                int* __restrict__ rowp, int* __restrict__ cursor, int n) {
    int i = blockIdx.x * blockDim.x + threadIdx.x;
    if (i == 0) rowp[0] = 0;
    if (i < n) {
        int incl = part[i] + bsum[i >> 8];
        rowp[i + 1] = incl;
        int v = (i & 255) ? (part[i - 1] + bsum[i >> 8]) : bsum[i >> 8];
        cursor[i] = v;
    }
}

__global__ void fill_k(const int* __restrict__ src, const int* __restrict__ dst,
                       int* __restrict__ cursor, int* __restrict__ esrc, int E) {
    int e = blockIdx.x * blockDim.x + threadIdx.x;
    if (e >= E) return;
    int d = dst[e];
    int p = atomicAdd(&cursor[d], 1);   // absolute slot
    esrc[p] = src[e];
}

// pad slack slots [cursor[i], rowp[i+1]) with the zero-row sentinel index.
__global__ void pad_k(const int* __restrict__ cursor, const int* __restrict__ rowp,
                      int* __restrict__ esrc, int n) {
    int i = blockIdx.x * blockDim.x + threadIdx.x;
    if (i >= n) return;
    int p = cursor[i], e = rowp[i + 1];
    for (; p < e; ++p) esrc[p] = n;     // sentinel = zero row
}

// ---------------- fp32 -> fp16 conversion (+ zero row n) ----------------
__global__ void f2h_k(const float* __restrict__ x, __half* __restrict__ xh, int n) {
    int i = blockIdx.x * blockDim.x + threadIdx.x;
    if (i < (n + 1) * 19)
        xh[i] = (i < n * 19) ? __float2half_rn(x[i]) : __ushort_as_half(0);
}

// ---------------- head precompute: v_m = W2@m_w, v_d = W2@d_w1 ----------------
__global__ void precomp_k(const float* __restrict__ W2, const float* __restrict__ b2,
                          const float* __restrict__ m_w, const float* __restrict__ m_b,
                          const float* __restrict__ d_w1,
                          float* __restrict__ vm, float* __restrict__ vd,
                          float* __restrict__ sc) {
    int i = threadIdx.x;  // 64 threads
    float am = 0.0f, ad = 0.0f;
    for (int k = 0; k < 64; ++k) {
        float w = W2[i * 64 + k];
        am += w * m_w[k];
        ad += w * d_w1[k];
    }
    vm[i] = am;
    vd[i] = ad;
    if (i == 0) {
        float sm = m_b[0], sd = 0.0f;
        for (int k = 0; k < 64; ++k) {
            sm += b2[k] * m_w[k];
            sd += b2[k] * d_w1[k];
        }
        sc[0] = sm;
        sc[1] = sd;
    }
}

// ---------------- aggregation kernels (warp per node; padded rows, uniform loops) -----
__global__ void agg19h_k(const __half* __restrict__ xh, const int* __restrict__ rowp,
                         const int* __restrict__ esrc, __half* __restrict__ z, int n) {
    int w = (blockIdx.x * blockDim.x + threadIdx.x) >> 5;
    int lane = threadIdx.x & 31;
    if (w >= n || lane >= 19) return;
    float acc = __half2float(xh[w * 19 + lane]);
    int s = rowp[w], e = rowp[w + 1];
    for (int j = s; j < e; j += 8) {
        int4 ia = *(const int4*)(esrc + j);
        int4 ib = *(const int4*)(esrc + j + 4);
        float a0 = __half2float(xh[ia.x * 19 + lane]);
        float a1 = __half2float(xh[ia.y * 19 + lane]);
        float a2 = __half2float(xh[ia.z * 19 + lane]);
        float a3 = __half2float(xh[ia.w * 19 + lane]);
        float a4 = __half2float(xh[ib.x * 19 + lane]);
        float a5 = __half2float(xh[ib.y * 19 + lane]);
        float a6 = __half2float(xh[ib.z * 19 + lane]);
        float a7 = __half2float(xh[ib.w * 19 + lane]);
        acc += a0; acc += a1; acc += a2; acc += a3;
        acc += a4; acc += a5; acc += a6; acc += a7;
    }
    z[w * 19 + lane] = __float2half_rn(acc);
}

__device__ __forceinline__ void acc_h4(float4& acc, uint2 v) {
    float2 f0 = __half22float2(*(__half2*)&v.x);
    float2 f1 = __half22float2(*(__half2*)&v.y);
    acc.x += f0.x; acc.y += f0.y; acc.z += f1.x; acc.w += f1.y;
}

// 128-dim fp16 gather -> fp16 z. Lane covers 4 features (uint2 = 8B). Uniform 8-deep.
__global__ void agg128h_k(const __half* __restrict__ h, const int* __restrict__ rowp,
                          const int* __restrict__ esrc, __half* __restrict__ z, int n) {
    int w = (blockIdx.x * blockDim.x + threadIdx.x) >> 5;
    int lane = threadIdx.x & 31;
    if (w >= n) return;
    const uint2* h4 = (const uint2*)h;
    float4 acc = make_float4(0.f, 0.f, 0.f, 0.f);
    acc_h4(acc, h4[w * 32 + lane]);
    int s = rowp[w], e = rowp[w + 1];
    for (int j = s; j < e; j += 8) {
        int4 ia = *(const int4*)(esrc + j);
        int4 ib = *(const int4*)(esrc + j + 4);
        uint2 v0 = h4[ia.x * 32 + lane];
        uint2 v1 = h4[ia.y * 32 + lane];
        uint2 v2 = h4[ia.z * 32 + lane];
        uint2 v3 = h4[ia.w * 32 + lane];
        uint2 v4 = h4[ib.x * 32 + lane];
        uint2 v5 = h4[ib.y * 32 + lane];
        uint2 v6 = h4[ib.z * 32 + lane];
        uint2 v7 = h4[ib.w * 32 + lane];
        acc_h4(acc, v0); acc_h4(acc, v1); acc_h4(acc, v2); acc_h4(acc, v3);
        acc_h4(acc, v4); acc_h4(acc, v5); acc_h4(acc, v6); acc_h4(acc, v7);
    }
    uint2 o;
    *(__half2*)&o.x = __floats2half2_rn(acc.x, acc.y);
    *(__half2*)&o.y = __floats2half2_rn(acc.z, acc.w);
    ((uint2*)z)[w * 32 + lane] = o;
}

// 64-dim fp16 gather + bias + ReLU + fused dual head dot products. Uniform 8-deep.
__global__ void agg64_heads_k(const __half* __restrict__ y, const int* __restrict__ rowp,
                              const int* __restrict__ esrc, const float* __restrict__ bias,
                              const float* __restrict__ vm, const float* __restrict__ vd,
                              const float* __restrict__ sc,
                              float* __restrict__ mmse_out, float* __restrict__ td, int n) {
    int w = (blockIdx.x * blockDim.x + threadIdx.x) >> 5;
    int lane = threadIdx.x & 31;
    if (w >= n) return;
    const __half2* h2 = (const __half2*)y;  // 32 half2 per row
    float2 acc = __half22float2(h2[w * 32 + lane]);
    int s = rowp[w], e = rowp[w + 1];
    for (int j = s; j < e; j += 8) {
        int4 ia = *(const int4*)(esrc + j);
        int4 ib = *(const int4*)(esrc + j + 4);
        float2 a = __half22float2(h2[ia.x * 32 + lane]);
        float2 b = __half22float2(h2[ia.y * 32 + lane]);
        float2 c = __half22float2(h2[ia.z * 32 + lane]);
        float2 d = __half22float2(h2[ia.w * 32 + lane]);
        float2 p = __half22float2(h2[ib.x * 32 + lane]);
        float2 q = __half22float2(h2[ib.y * 32 + lane]);
        float2 r = __half22float2(h2[ib.z * 32 + lane]);
        float2 t = __half22float2(h2[ib.w * 32 + lane]);
        acc.x += a.x; acc.y += a.y; acc.x += b.x; acc.y += b.y;
        acc.x += c.x; acc.y += c.y; acc.x += d.x; acc.y += d.y;
        acc.x += p.x; acc.y += p.y; acc.x += q.x; acc.y += q.y;
        acc.x += r.x; acc.y += r.y; acc.x += t.x; acc.y += t.y;
    }
    float ux = fmaxf(acc.x + bias[lane * 2], 0.0f);
    float uy = fmaxf(acc.y + bias[lane * 2 + 1], 0.0f);
    float dm = ux * vm[lane * 2] + uy * vm[lane * 2 + 1];
    float dd = ux * vd[lane * 2] + uy * vd[lane * 2 + 1];
#pragma unroll
    for (int o = 16; o; o >>= 1) {
        dm += __shfl_down_sync(0xffffffffu, dm, o);
        dd += __shfl_down_sync(0xffffffffu, dd, o);
    }
    if (lane == 0) {
        float m = dm + sc[0];
        mmse_out[w] = (m > 0.0f) ? m : 0.01f * m;
        td[w] = dd + sc[1];
    }
}

__global__ void discrim_k(const float* __restrict__ td, const int* __restrict__ rowp,
                          const int* __restrict__ esrc, const float* __restrict__ d_b1,
                          const float* __restrict__ d_w2, const float* __restrict__ d_b2,
                          float* __restrict__ out, int n) {
    int i = blockIdx.x * blockDim.x + threadIdx.x;
    if (i >= n) return;
    float acc = td[i];
    int s = rowp[i], e = rowp[i + 1];
    for (int j = s; j < e; j += 8) {
        int4 ia = *(const int4*)(esrc + j);
        int4 ib = *(const int4*)(esrc + j + 4);
        float a = td[ia.x], b = td[ia.y], c = td[ia.z], d = td[ia.w];
        float p = td[ib.x], q = td[ib.y], r = td[ib.z], t = td[ib.w];
        acc += a; acc += b; acc += c; acc += d;
        acc += p; acc += q; acc += r; acc += t;
    }
    float u = acc + d_b1[0];
    u = fmaxf(u, 0.0f);
    out[i] = u * d_w2[0] + d_b2[0];
}

// ---------------- fp16 tensor-core GEMM (m16n8k16, ldmatrix, 128-row tiles) ----------------
__device__ __forceinline__ void ldsm4(uint32_t& r0, uint32_t& r1, uint32_t& r2, uint32_t& r3,
                                      uint32_t addr) {
    asm volatile("ldmatrix.sync.aligned.m8n8.x4.shared.b16 {%0,%1,%2,%3}, [%4];"
                 : "=r"(r0), "=r"(r1), "=r"(r2), "=r"(r3) : "r"(addr));
}

// C[n,OUT] = act(A[n,IN] @ W[IN,OUT] + bias); A fp16, W fp32->fp16, C fp16.
template <int IN, int OUT, bool RELU>
__global__ void gemm_h_k(const __half* __restrict__ A, const float* __restrict__ W,
                         const float* __restrict__ bias, __half* __restrict__ C, int n) {
    constexpr int KP = ((IN + 15) / 16) * 16;   // 32 / 128
    constexpr int STR = KP + 8;                 // padded k-stride in halfs
    constexpr int NT = OUT / 16;                // n8-tiles per warp

    extern __shared__ __half smh[];
    __half* Ws = smh;                           // [OUT][STR]
    __half* As = smh + OUT * STR;               // [128][STR]
    float* Bs = (float*)(smh + OUT * STR + 128 * STR);

    int tid = threadIdx.x;
    int row0 = blockIdx.x * 128;

    // stage W transposed: Ws[col][k]
    for (int i = tid; i < IN * OUT; i += 256) {
        int k = i / OUT, col = i - k * OUT;
        Ws[col * STR + k] = __float2half_rn(W[i]);
    }
    if (KP > IN) {
        for (int i = tid; i < (KP - IN) * OUT; i += 256) {
            int col = i % OUT, k = IN + i / OUT;
            Ws[col * STR + k] = __ushort_as_half(0);
        }
    }
    for (int i = tid; i < OUT; i += 256) Bs[i] = bias ? bias[i] : 0.0f;

    // stage A tile
    if (IN % 2 == 0) {
        constexpr int E2 = IN / 2;
        const uint32_t* A32 = (const uint32_t*)A;
        for (int i = tid; i < 128 * E2; i += 256) {
            int r = i / E2, kk = i - r * E2;
            int row = row0 + r;
            ((uint32_t*)(As + r * STR))[kk] = (row < n) ? A32[(size_t)row * E2 + kk] : 0u;
        }
    } else {
        for (int i = tid; i < 128 * IN; i += 256) {
            int r = i / IN, k = i - r * IN;
            int row = row0 + r;
            As[r * STR + k] = (row < n) ? A[(size_t)row * IN + k] : __ushort_as_half(0);
        }
    }
    if (KP > IN) {
        for (int i = tid; i < 128 * (KP - IN); i += 256) {
            int r = i / (KP - IN), k = IN + i % (KP - IN);
            As[r * STR + k] = __ushort_as_half(0);
        }
    }
    __syncthreads();

    int w = tid >> 5, lane = tid & 31;
    int wm = w >> 1, wn = w & 1;                // 4 x 2 warp grid
    int g = lane >> 2, t4 = lane & 3;
    int rbase = wm * 32, cbase = wn * (OUT / 2);

    int q = lane & 7, set = lane >> 3;          // ldmatrix lane roles
    uint32_t aA0 = (uint32_t)__cvta_generic_to_shared(
        As + (rbase + (set & 1) * 8 + q) * STR + (set >> 1) * 8);
    uint32_t aA1 = aA0 + 16 * STR * 2;
    uint32_t aB[NT / 2];
#pragma unroll
    for (int p = 0; p < NT / 2; ++p)
        aB[p] = (uint32_t)__cvta_generic_to_shared(
            Ws + (cbase + p * 16 + (set >> 1) * 8 + q) * STR + (set & 1) * 8);

    float acc[2][NT][4];
#pragma unroll
    for (int mt = 0; mt < 2; ++mt)
#pragma unroll
        for (int nt = 0; nt < NT; ++nt)
#pragma unroll
            for (int z = 0; z < 4; ++z) acc[mt][nt][z] = 0.0f;

#pragma unroll
    for (int k0 = 0; k0 < KP; k0 += 16) {
        uint32_t a[2][4];
        ldsm4(a[0][0], a[0][1], a[0][2], a[0][3], aA0 + k0 * 2);
        ldsm4(a[1][0], a[1][1], a[1][2], a[1][3], aA1 + k0 * 2);
        uint32_t b[NT][2];
#pragma unroll
        for (int p = 0; p < NT / 2; ++p) {
            uint32_t r0, r1, r2, r3;
            ldsm4(r0, r1, r2, r3, aB[p] + k0 * 2);
            b[2 * p][0] = r0; b[2 * p][1] = r1;
            b[2 * p + 1][0] = r2; b[2 * p + 1][1] = r3;
        }
#pragma unroll
        for (int mt = 0; mt < 2; ++mt)
#pragma unroll
            for (int nt = 0; nt < NT; ++nt) {
                asm volatile(
                    "mma.sync.aligned.m16n8k16.row.col.f32.f16.f16.f32 "
                    "{%0,%1,%2,%3}, {%4,%5,%6,%7}, {%8,%9}, {%0,%1,%2,%3};\n"
                    : "+f"(acc[mt][nt][0]), "+f"(acc[mt][nt][1]),
                      "+f"(acc[mt][nt][2]), "+f"(acc[mt][nt][3])
                    : "r"(a[mt][0]), "r"(a[mt][1]), "r"(a[mt][2]), "r"(a[mt][3]),
                      "r"(b[nt][0]), "r"(b[nt][1]));
            }
    }

    // epilogue: bias + optional relu -> fp16
#pragma unroll
    for (int mt = 0; mt < 2; ++mt) {
        int r1 = row0 + rbase + mt * 16 + g;
#pragma unroll
        for (int nt = 0; nt < NT; ++nt) {
            int col = cbase + nt * 8 + t4 * 2;
            float b0 = Bs[col], b1 = Bs[col + 1];
            if (r1 < n) {
                float v0 = acc[mt][nt][0] + b0;
                float v1 = acc[mt][nt][1] + b1;
                if (RELU) { v0 = fmaxf(v0, 0.0f); v1 = fmaxf(v1, 0.0f); }
                *(__half2*)(C + (size_t)r1 * OUT + col) = __floats2half2_rn(v0, v1);
            }
            if (r1 + 8 < n) {
                float v2 = acc[mt][nt][2] + b0;
                float v3 = acc[mt][nt][3] + b1;
                if (RELU) { v2 = fmaxf(v2, 0.0f); v3 = fmaxf(v3, 0.0f); }
                *(__half2*)(C + (size_t)(r1 + 8) * OUT + col) = __floats2half2_rn(v2, v3);
            }
        }
    }
}

// ---------------- host ----------------
template <int IN, int OUT, bool RELU>
static void launch_gemm_h(const __half* A, const float* W, const float* bias,
                          __half* C, int n) {
    constexpr int KP = ((IN + 15) / 16) * 16;
    constexpr int STR = KP + 8;
    size_t smb = (size_t)(OUT * STR + 128 * STR) * sizeof(__half) + OUT * sizeof(float);
    cudaFuncSetAttribute(gemm_h_k<IN, OUT, RELU>,
                         cudaFuncAttributeMaxDynamicSharedMemorySize, (int)smb);
    gemm_h_k<IN, OUT, RELU><<<(n + 127) / 128, 256, smb>>>(A, W, bias, C, n);
}

extern "C" void kernel_launch(void* const* d_in, const int* in_sizes, int n_in,
                              void* d_out, int out_size) {
    const float* x   = (const float*)d_in[0];
    const int*   ei  = (const int*)d_in[1];
    const int E = in_sizes[1] / 2;
    const int n = in_sizes[0] / 19;
    const int* src = ei;
    const int* dst = ei + E;

    const float* l0w1 = (const float*)d_in[2];
    const float* l0b1 = (const float*)d_in[3];
    const float* l0w2 = (const float*)d_in[4];
    const float* l0b2 = (const float*)d_in[5];
    const float* l1w1 = (const float*)d_in[6];
    const float* l1b1 = (const float*)d_in[7];
    const float* l1w2 = (const float*)d_in[8];
    const float* l1b2 = (const float*)d_in[9];
    const float* l2w1 = (const float*)d_in[10];
    const float* l2b1 = (const float*)d_in[11];
    const float* l2w2 = (const float*)d_in[12];
    const float* l2b2 = (const float*)d_in[13];
    const float* l3w1 = (const float*)d_in[14];
    const float* l3b1 = (const float*)d_in[15];
    const float* l3w2 = (const float*)d_in[16];
    const float* l3b2 = (const float*)d_in[17];
    const float* m_w  = (const float*)d_in[18];
    const float* m_b  = (const float*)d_in[19];
    const float* d_w1 = (const float*)d_in[20];
    const float* d_b1 = (const float*)d_in[21];
    const float* d_w2 = (const float*)d_in[22];
    const float* d_b2 = (const float*)d_in[23];

    void *pH, *pZ, *pT, *pX, *pVm, *pVd, *pSc, *pTd, *pRow, *pCnt, *pCur, *pPart, *pBsum, *pEsrc;
    cudaGetSymbolAddress(&pH, g_h16);
    cudaGetSymbolAddress(&pZ, g_z16);
    cudaGetSymbolAddress(&pT, g_t16);
    cudaGetSymbolAddress(&pX, g_x16);
    cudaGetSymbolAddress(&pVm, g_vm);
    cudaGetSymbolAddress(&pVd, g_vd);
    cudaGetSymbolAddress(&pSc, g_sc);
    cudaGetSymbolAddress(&pTd, g_td);
    cudaGetSymbolAddress(&pRow, g_rowp);
    cudaGetSymbolAddress(&pCnt, g_cnt);
    cudaGetSymbolAddress(&pCur, g_cur);
    cudaGetSymbolAddress(&pPart, g_part);
    cudaGetSymbolAddress(&pBsum, g_bsum);
    cudaGetSymbolAddress(&pEsrc, g_esrc);
    __half* h16 = (__half*)pH;
    __half* z16 = (__half*)pZ;
    __half* t16 = (__half*)pT;
    __half* x16 = (__half*)pX;
    float* vm = (float*)pVm;
    float* vd = (float*)pVd;
    float* sc = (float*)pSc;
    float* td = (float*)pTd;
    int* rowp = (int*)pRow;
    int* cnt  = (int*)pCnt;
    int* cur  = (int*)pCur;
    int* part = (int*)pPart;
    int* bsum = (int*)pBsum;
    int* esrc = (int*)pEsrc;

    float* out = (float*)d_out;

    const int TB = 256;
    const int edgeBlocks = (E + TB - 1) / TB;
    const int nodeBlocks = (n + TB - 1) / TB;
    const int warpBlocks = (n * 32 + TB - 1) / TB;  // warp per node
    const int nb = (n + 255) / 256;

    // ---- independent precomputes + zero rows ----
    f2h_k<<<((n + 1) * 19 + 255) / 256, 256>>>(x, x16, n);
    precomp_k<<<1, 64>>>(l3w2, l3b2, m_w, m_b, d_w1, vm, vd, sc);
    cudaMemsetAsync(h16 + (size_t)n * 128, 0, 128 * sizeof(__half)); // zero row (128-dim view)
    cudaMemsetAsync(td + n, 0, sizeof(float));                       // td sentinel

    // ---- CSR build (padded to multiples of 8, sentinel n) ----
    cudaMemsetAsync(cnt, 0, (size_t)n * sizeof(int));
    count_k<<<(E / 4 + TB - 1) / TB, TB>>>(dst, cnt, E);
    block_scan_k<<<nb, 256>>>(cnt, part, bsum, n);
    scan_bsum_k<<<1, 256>>>(bsum, nb);
    finalize_rowp_k<<<nodeBlocks, TB>>>(part, bsum, rowp, cur, n);
    fill_k<<<edgeBlocks, TB>>>(src, dst, cur, esrc, E);
    pad_k<<<nodeBlocks, TB>>>(cur, rowp, esrc, n);

    // ---- layer 0 ----
    agg19h_k<<<warpBlocks, TB>>>(x16, rowp, esrc, z16, n);
    launch_gemm_h<19, 128, true>(z16, l0w1, l0b1, t16, n);
    launch_gemm_h<128, 128, true>(t16, l0w2, l0b2, h16, n);   // h0 fp16 (relu folded)

    // ---- layer 1 ----
    agg128h_k<<<warpBlocks, TB>>>(h16, rowp, esrc, z16, n);
    launch_gemm_h<128, 128, true>(z16, l1w1, l1b1, t16, n);
    launch_gemm_h<128, 128, true>(t16, l1w2, l1b2, h16, n);   // h1 fp16

    // ---- layer 2 ----
    agg128h_k<<<warpBlocks, TB>>>(h16, rowp, esrc, z16, n);
    launch_gemm_h<128, 128, true>(z16, l2w1, l2b1, t16, n);
    launch_gemm_h<128, 128, true>(t16, l2w2, l2b2, z16, n);   // h2 fp16 (into z16)

    // ---- layer 3: y = h2 @ W1 (64-dim fp16 in h16), zero y row n, agg + heads ----
    launch_gemm_h<128, 64, false>(z16, l3w1, nullptr, h16, n); // y fp16
    cudaMemsetAsync(h16 + (size_t)n * 64, 0, 64 * sizeof(__half)); // zero row (64-dim view)
    agg64_heads_k<<<warpBlocks, TB>>>(h16, rowp, esrc, l3b1, vm, vd, sc,
                                      out + n, td, n);

    // ---- discriminator ----
    discrim_k<<<nodeBlocks, TB>>>(td, rowp, esrc, d_b1, d_w2, d_b2, out, n);
}

// round 14
// speedup vs baseline: 1.1045x; 1.1045x over previous
#include <cuda_runtime.h>
#include <cuda_fp16.h>
#include <cstdint>

#define NN 50000
#define NE 1600000

// Wt16 layout offsets (halfs): [col*STR + k], STR = KP+8
#define W0A_OFF 0                      // l0w1: 19->128,  KP=32,  STR=40,  128*40  = 5120
#define W0B_OFF 5120                   // l0w2: 128->128, STR=136, 128*136 = 17408
#define W1A_OFF (W0B_OFF + 17408)
#define W1B_OFF (W1A_OFF + 17408)
#define W2A_OFF (W1B_OFF + 17408)
#define W2B_OFF (W2A_OFF + 17408)
#define W3A_OFF (W2B_OFF + 17408)      // l3w1: 128->64, 64*136 = 8704
#define WT_TOTAL (W3A_OFF + 8704)

// ---------------- scratch (static device globals; no allocs allowed) ----------------
__device__ __half g_h16[NN * 128];   // gather source / y
__device__ __half g_z16[NN * 128];   // agg output / GEMM input
__device__ __half g_t16[NN * 128];   // MLP intermediate
__device__ __half g_x16[NN * 19];
__device__ __half g_w16[WT_TOTAL];   // pre-transposed fp16 weights
__device__ float  g_vm[64];
__device__ float  g_vd[64];
__device__ float  g_sc[2];
__device__ float  g_td[NN];
__device__ int    g_rowp[NN + 1];
__device__ int    g_cnt[NN];
__device__ int    g_cur[NN];
__device__ int    g_part[NN];
__device__ int    g_bsum[256];
__device__ int    g_esrc[NE];

// ---------------- CSR build ----------------
__global__ void count_k(const int* __restrict__ dst, int* __restrict__ cnt, int E) {
    int base = (blockIdx.x * blockDim.x + threadIdx.x) * 4;
    if (base + 4 <= E) {
        int4 d = *(const int4*)(dst + base);
        atomicAdd(&cnt[d.x], 1);
        atomicAdd(&cnt[d.y], 1);
        atomicAdd(&cnt[d.z], 1);
        atomicAdd(&cnt[d.w], 1);
    } else {
        for (int e = base; e < E; ++e) atomicAdd(&cnt[dst[e]], 1);
    }
}

__global__ void block_scan_k(const int* __restrict__ cnt, int* __restrict__ part,
                             int* __restrict__ bsum, int n) {
    __shared__ int wsum[8];
    int t = threadIdx.x;
    int i = blockIdx.x * 256 + t;
    int v = (i < n) ? cnt[i] : 0;
    int lane = t & 31, w = t >> 5;
    int x = v;
#pragma unroll
    for (int o = 1; o < 32; o <<= 1) {
        int y = __shfl_up_sync(0xffffffffu, x, o);
        if (lane >= o) x += y;
    }
    if (lane == 31) wsum[w] = x;
    __syncthreads();
    if (w == 0) {
        int s = (lane < 8) ? wsum[lane] : 0;
#pragma unroll
        for (int o = 1; o < 8; o <<= 1) {
            int y = __shfl_up_sync(0xffffffffu, s, o);
            if (lane >= o) s += y;
        }
        if (lane < 8) wsum[lane] = s;
    }
    __syncthreads();
    if (w > 0) x += wsum[w - 1];
    if (i < n) part[i] = x;
    if (t == 255) bsum[blockIdx.x] = x;
}

__global__ void scan_bsum_k(int* __restrict__ bsum, int nb) {
    __shared__ int wsum[8];
    int t = threadIdx.x;
    int v = (t < nb) ? bsum[t] : 0;
    int lane = t & 31, w = t >> 5;
    int x = v;
#pragma unroll
    for (int o = 1; o < 32; o <<= 1) {
        int y = __shfl_up_sync(0xffffffffu, x, o);
        if (lane >= o) x += y;
    }
    if (lane == 31) wsum[w] = x;
    __syncthreads();
    if (w == 0) {
        int s = (lane < 8) ? wsum[lane] : 0;
#pragma unroll
        for (int o = 1; o < 8; o <<= 1) {
            int y = __shfl_up_sync(0xffffffffu, s, o);
            if (lane >= o) s += y;
        }
        if (lane < 8) wsum[lane] = s;
    }
    __syncthreads();
    if (w > 0) x += wsum[w - 1];
    if (t < nb) bsum[t] = x - v;   // exclusive
}

// rowp[i+1] = inclusive scan; cursor[i] = exclusive scan (= rowp[i]).
__global__ void finalize_rowp_k(const int* __restrict__ part, const int* __restrict__ bsum,
                                int* __restrict__ rowp, int* __restrict__ cursor, int n) {
    int i = blockIdx.x * blockDim.x + threadIdx.x;
    if (i == 0) rowp[0] = 0;
    if (i < n) {
        int incl = part[i] + bsum[i >> 8];
        rowp[i + 1] = incl;
        int v = (i & 255) ? (part[i - 1] + bsum[i >> 8]) : bsum[i >> 8];
        cursor[i] = v;
    }
}

__global__ void fill_k(const int* __restrict__ src, const int* __restrict__ dst,
                       int* __restrict__ cursor, int* __restrict__ esrc, int E) {
    int e = blockIdx.x * blockDim.x + threadIdx.x;
    if (e >= E) return;
    int d = dst[e];
    int p = atomicAdd(&cursor[d], 1);   // absolute slot
    esrc[p] = src[e];
}

// ---------------- fp32 -> fp16 conversion ----------------
__global__ void f2h_k(const float* __restrict__ x, __half* __restrict__ xh, int n) {
    int i = blockIdx.x * blockDim.x + threadIdx.x;
    if (i < n) xh[i] = __float2half_rn(x[i]);
}

// ---------------- weight pre-transpose: Wt[col*STR + k] = fp16(W[k*OUT + col]) ----------
__global__ void conv_w_k(const float* __restrict__ W, __half* __restrict__ Wt,
                         int IN, int OUT, int STR) {
    int idx = blockIdx.x * blockDim.x + threadIdx.x;
    if (idx >= OUT * STR) return;
    int col = idx / STR, kk = idx - col * STR;
    Wt[idx] = (kk < IN) ? __float2half_rn(W[kk * OUT + col]) : __ushort_as_half(0);
}

// ---------------- head precompute: v_m = W2@m_w, v_d = W2@d_w1 ----------------
__global__ void precomp_k(const float* __restrict__ W2, const float* __restrict__ b2,
                          const float* __restrict__ m_w, const float* __restrict__ m_b,
                          const float* __restrict__ d_w1,
                          float* __restrict__ vm, float* __restrict__ vd,
                          float* __restrict__ sc) {
    int i = threadIdx.x;  // 64 threads
    float am = 0.0f, ad = 0.0f;
    for (int k = 0; k < 64; ++k) {
        float w = W2[i * 64 + k];
        am += w * m_w[k];
        ad += w * d_w1[k];
    }
    vm[i] = am;
    vd[i] = ad;
    if (i == 0) {
        float sm = m_b[0], sd = 0.0f;
        for (int k = 0; k < 64; ++k) {
            sm += b2[k] * m_w[k];
            sd += b2[k] * d_w1[k];
        }
        sc[0] = sm;
        sc[1] = sd;
    }
}

// ---------------- aggregation kernels (R10-proven shapes) ----------------
__global__ void agg19h_k(const __half* __restrict__ xh, const int* __restrict__ rowp,
                         const int* __restrict__ esrc, __half* __restrict__ z, int n) {
    int w = (blockIdx.x * blockDim.x + threadIdx.x) >> 5;
    int lane = threadIdx.x & 31;
    if (w >= n || lane >= 19) return;
    float acc = __half2float(xh[w * 19 + lane]);
    int s = rowp[w], e = rowp[w + 1];
    int j = s;
    for (; j + 4 <= e; j += 4) {
        int s0 = esrc[j], s1 = esrc[j + 1], s2 = esrc[j + 2], s3 = esrc[j + 3];
        float a = __half2float(xh[s0 * 19 + lane]);
        float b = __half2float(xh[s1 * 19 + lane]);
        float c = __half2float(xh[s2 * 19 + lane]);
        float d = __half2float(xh[s3 * 19 + lane]);
        acc += a; acc += b; acc += c; acc += d;
    }
    for (; j < e; ++j) acc += __half2float(xh[esrc[j] * 19 + lane]);
    z[w * 19 + lane] = __float2half_rn(acc);
}

__device__ __forceinline__ void acc_h4(float4& acc, uint2 v) {
    float2 f0 = __half22float2(*(__half2*)&v.x);
    float2 f1 = __half22float2(*(__half2*)&v.y);
    acc.x += f0.x; acc.y += f0.y; acc.z += f1.x; acc.w += f1.y;
}

__global__ void agg128h_k(const __half* __restrict__ h, const int* __restrict__ rowp,
                          const int* __restrict__ esrc, __half* __restrict__ z, int n) {
    int w = (blockIdx.x * blockDim.x + threadIdx.x) >> 5;
    int lane = threadIdx.x & 31;
    if (w >= n) return;
    const uint2* h4 = (const uint2*)h;
    float4 acc = make_float4(0.f, 0.f, 0.f, 0.f);
    acc_h4(acc, h4[w * 32 + lane]);
    int s = rowp[w], e = rowp[w + 1];
    int j = s;
    for (; j + 8 <= e; j += 8) {
        int i0 = esrc[j],     i1 = esrc[j + 1], i2 = esrc[j + 2], i3 = esrc[j + 3];
        int i4 = esrc[j + 4], i5 = esrc[j + 5], i6 = esrc[j + 6], i7 = esrc[j + 7];
        uint2 v0 = h4[i0 * 32 + lane];
        uint2 v1 = h4[i1 * 32 + lane];
        uint2 v2 = h4[i2 * 32 + lane];
        uint2 v3 = h4[i3 * 32 + lane];
        uint2 v4 = h4[i4 * 32 + lane];
        uint2 v5 = h4[i5 * 32 + lane];
        uint2 v6 = h4[i6 * 32 + lane];
        uint2 v7 = h4[i7 * 32 + lane];
        acc_h4(acc, v0); acc_h4(acc, v1); acc_h4(acc, v2); acc_h4(acc, v3);
        acc_h4(acc, v4); acc_h4(acc, v5); acc_h4(acc, v6); acc_h4(acc, v7);
    }
    for (; j < e; ++j) acc_h4(acc, h4[esrc[j] * 32 + lane]);
    uint2 o;
    *(__half2*)&o.x = __floats2half2_rn(acc.x, acc.y);
    *(__half2*)&o.y = __floats2half2_rn(acc.z, acc.w);
    ((uint2*)z)[w * 32 + lane] = o;
}

__global__ void agg64_heads_k(const __half* __restrict__ y, const int* __restrict__ rowp,
                              const int* __restrict__ esrc, const float* __restrict__ bias,
                              const float* __restrict__ vm, const float* __restrict__ vd,
                              const float* __restrict__ sc,
                              float* __restrict__ mmse_out, float* __restrict__ td, int n) {
    int w = (blockIdx.x * blockDim.x + threadIdx.x) >> 5;
    int lane = threadIdx.x & 31;
    if (w >= n) return;
    const __half2* h2 = (const __half2*)y;  // 32 half2 per row
    float2 acc = __half22float2(h2[w * 32 + lane]);
    int s = rowp[w], e = rowp[w + 1];
    int j = s;
    for (; j + 8 <= e; j += 8) {
        int i0 = esrc[j],     i1 = esrc[j + 1], i2 = esrc[j + 2], i3 = esrc[j + 3];
        int i4 = esrc[j + 4], i5 = esrc[j + 5], i6 = esrc[j + 6], i7 = esrc[j + 7];
        float2 a = __half22float2(h2[i0 * 32 + lane]);
        float2 b = __half22float2(h2[i1 * 32 + lane]);
        float2 c = __half22float2(h2[i2 * 32 + lane]);
        float2 d = __half22float2(h2[i3 * 32 + lane]);
        float2 p = __half22float2(h2[i4 * 32 + lane]);
        float2 q = __half22float2(h2[i5 * 32 + lane]);
        float2 r = __half22float2(h2[i6 * 32 + lane]);
        float2 t = __half22float2(h2[i7 * 32 + lane]);
        acc.x += a.x; acc.y += a.y; acc.x += b.x; acc.y += b.y;
        acc.x += c.x; acc.y += c.y; acc.x += d.x; acc.y += d.y;
        acc.x += p.x; acc.y += p.y; acc.x += q.x; acc.y += q.y;
        acc.x += r.x; acc.y += r.y; acc.x += t.x; acc.y += t.y;
    }
    for (; j < e; ++j) {
        float2 f = __half22float2(h2[esrc[j] * 32 + lane]);
        acc.x += f.x; acc.y += f.y;
    }
    float ux = fmaxf(acc.x + bias[lane * 2], 0.0f);
    float uy = fmaxf(acc.y + bias[lane * 2 + 1], 0.0f);
    float dm = ux * vm[lane * 2] + uy * vm[lane * 2 + 1];
    float dd = ux * vd[lane * 2] + uy * vd[lane * 2 + 1];
#pragma unroll
    for (int o = 16; o; o >>= 1) {
        dm += __shfl_down_sync(0xffffffffu, dm, o);
        dd += __shfl_down_sync(0xffffffffu, dd, o);
    }
    if (lane == 0) {
        float m = dm + sc[0];
        mmse_out[w] = (m > 0.0f) ? m : 0.01f * m;
        td[w] = dd + sc[1];
    }
}

__global__ void discrim_k(const float* __restrict__ td, const int* __restrict__ rowp,
                          const int* __restrict__ esrc, const float* __restrict__ d_b1,
                          const float* __restrict__ d_w2, const float* __restrict__ d_b2,
                          float* __restrict__ out, int n) {
    int i = blockIdx.x * blockDim.x + threadIdx.x;
    if (i >= n) return;
    float acc = td[i];
    int s = rowp[i], e = rowp[i + 1];
    int j = s;
    for (; j + 4 <= e; j += 4) {
        float a = td[esrc[j]], b = td[esrc[j + 1]];
        float c = td[esrc[j + 2]], d = td[esrc[j + 3]];
        acc += a; acc += b; acc += c; acc += d;
    }
    for (; j < e; ++j) acc += td[esrc[j]];
    float u = acc + d_b1[0];
    u = fmaxf(u, 0.0f);
    out[i] = u * d_w2[0] + d_b2[0];
}

// ---------------- fp16 tensor-core GEMM (m16n8k16, ldmatrix, pre-staged weights) ------
__device__ __forceinline__ void ldsm4(uint32_t& r0, uint32_t& r1, uint32_t& r2, uint32_t& r3,
                                      uint32_t addr) {
    asm volatile("ldmatrix.sync.aligned.m8n8.x4.shared.b16 {%0,%1,%2,%3}, [%4];"
                 : "=r"(r0), "=r"(r1), "=r"(r2), "=r"(r3) : "r"(addr));
}

// C[n,OUT] = act(A[n,IN] @ Wt + bias); Wt pre-transposed fp16 in smem layout [col*STR+k].
template <int IN, int OUT, bool RELU>
__global__ void gemm_h_k(const __half* __restrict__ A, const __half* __restrict__ Wt,
                         const float* __restrict__ bias, __half* __restrict__ C, int n) {
    constexpr int KP = ((IN + 15) / 16) * 16;   // 32 / 128
    constexpr int STR = KP + 8;                 // padded k-stride in halfs
    constexpr int NT = OUT / 16;                // n8-tiles per warp
    constexpr int WSZ4 = OUT * STR / 8;         // W size in uint4

    extern __shared__ __half smh[];
    __half* Ws = smh;                           // [OUT][STR]
    __half* As = smh + OUT * STR;               // [128][STR]
    float* Bs = (float*)(smh + OUT * STR + 128 * STR);

    int tid = threadIdx.x;
    int row0 = blockIdx.x * 128;

    // stage W: straight uint4 copy (layout already matches)
    {
        const uint4* Wg = (const uint4*)Wt;
        uint4* Wsm = (uint4*)Ws;
        for (int i = tid; i < WSZ4; i += 256) Wsm[i] = Wg[i];
    }
    for (int i = tid; i < OUT; i += 256) Bs[i] = bias ? bias[i] : 0.0f;

    // stage A tile
    if (IN == 128) {
        // 16 uint4 per row; smem row start = r*STR*2 = r*272 bytes (16B aligned)
        const uint4* A4 = (const uint4*)A;
        for (int i = tid; i < 128 * 16; i += 256) {
            int r = i >> 4, kk = i & 15;
            int row = row0 + r;
            uint4 v = (row < n) ? A4[(size_t)row * 16 + kk] : make_uint4(0u, 0u, 0u, 0u);
            ((uint4*)(As + r * STR))[kk] = v;
        }
    } else {
        for (int i = tid; i < 128 * IN; i += 256) {
            int r = i / IN, k = i - r * IN;
            int row = row0 + r;
            As[r * STR + k] = (row < n) ? A[(size_t)row * IN + k] : __ushort_as_half(0);
        }
        for (int i = tid; i < 128 * (KP - IN); i += 256) {
            int r = i / (KP - IN), k = IN + i % (KP - IN);
            As[r * STR + k] = __ushort_as_half(0);
        }
    }
    __syncthreads();

    int w = tid >> 5, lane = tid & 31;
    int wm = w >> 1, wn = w & 1;                // 4 x 2 warp grid
    int g = lane >> 2, t4 = lane & 3;
    int rbase = wm * 32, cbase = wn * (OUT / 2);

    int q = lane & 7, set = lane >> 3;          // ldmatrix lane roles
    uint32_t aA0 = (uint32_t)__cvta_generic_to_shared(
        As + (rbase + (set & 1) * 8 + q) * STR + (set >> 1) * 8);
    uint32_t aA1 = aA0 + 16 * STR * 2;
    uint32_t aB[NT / 2];
#pragma unroll
    for (int p = 0; p < NT / 2; ++p)
        aB[p] = (uint32_t)__cvta_generic_to_shared(
            Ws + (cbase + p * 16 + (set >> 1) * 8 + q) * STR + (set & 1) * 8);

    float acc[2][NT][4];
#pragma unroll
    for (int mt = 0; mt < 2; ++mt)
#pragma unroll
        for (int nt = 0; nt < NT; ++nt)
#pragma unroll
            for (int z = 0; z < 4; ++z) acc[mt][nt][z] = 0.0f;

#pragma unroll
    for (int k0 = 0; k0 < KP; k0 += 16) {
        uint32_t a[2][4];
        ldsm4(a[0][0], a[0][1], a[0][2], a[0][3], aA0 + k0 * 2);
        ldsm4(a[1][0], a[1][1], a[1][2], a[1][3], aA1 + k0 * 2);
        uint32_t b[NT][2];
#pragma unroll
        for (int p = 0; p < NT / 2; ++p) {
            uint32_t r0, r1, r2, r3;
            ldsm4(r0, r1, r2, r3, aB[p] + k0 * 2);
            b[2 * p][0] = r0; b[2 * p][1] = r1;
            b[2 * p + 1][0] = r2; b[2 * p + 1][1] = r3;
        }
#pragma unroll
        for (int mt = 0; mt < 2; ++mt)
#pragma unroll
            for (int nt = 0; nt < NT; ++nt) {
                asm volatile(
                    "mma.sync.aligned.m16n8k16.row.col.f32.f16.f16.f32 "
                    "{%0,%1,%2,%3}, {%4,%5,%6,%7}, {%8,%9}, {%0,%1,%2,%3};\n"
                    : "+f"(acc[mt][nt][0]), "+f"(acc[mt][nt][1]),
                      "+f"(acc[mt][nt][2]), "+f"(acc[mt][nt][3])
                    : "r"(a[mt][0]), "r"(a[mt][1]), "r"(a[mt][2]), "r"(a[mt][3]),
                      "r"(b[nt][0]), "r"(b[nt][1]));
            }
    }

    // epilogue: bias + optional relu -> fp16
#pragma unroll
    for (int mt = 0; mt < 2; ++mt) {
        int r1 = row0 + rbase + mt * 16 + g;
#pragma unroll
        for (int nt = 0; nt < NT; ++nt) {
            int col = cbase + nt * 8 + t4 * 2;
            float b0 = Bs[col], b1 = Bs[col + 1];
            if (r1 < n) {
                float v0 = acc[mt][nt][0] + b0;
                float v1 = acc[mt][nt][1] + b1;
                if (RELU) { v0 = fmaxf(v0, 0.0f); v1 = fmaxf(v1, 0.0f); }
                *(__half2*)(C + (size_t)r1 * OUT + col) = __floats2half2_rn(v0, v1);
            }
            if (r1 + 8 < n) {
                float v2 = acc[mt][nt][2] + b0;
                float v3 = acc[mt][nt][3] + b1;
                if (RELU) { v2 = fmaxf(v2, 0.0f); v3 = fmaxf(v3, 0.0f); }
                *(__half2*)(C + (size_t)(r1 + 8) * OUT + col) = __floats2half2_rn(v2, v3);
            }
        }
    }
}

// ---------------- host ----------------
template <int IN, int OUT, bool RELU>
static void launch_gemm_h(const __half* A, const __half* Wt, const float* bias,
                          __half* C, int n) {
    constexpr int KP = ((IN + 15) / 16) * 16;
    constexpr int STR = KP + 8;
    size_t smb = (size_t)(OUT * STR + 128 * STR) * sizeof(__half) + OUT * sizeof(float);
    cudaFuncSetAttribute(gemm_h_k<IN, OUT, RELU>,
                         cudaFuncAttributeMaxDynamicSharedMemorySize, (int)smb);
    gemm_h_k<IN, OUT, RELU><<<(n + 127) / 128, 256, smb>>>(A, Wt, bias, C, n);
}

static void launch_conv_w(const float* W, __half* Wt, int IN, int OUT, int STR) {
    int total = OUT * STR;
    conv_w_k<<<(total + 255) / 256, 256>>>(W, Wt, IN, OUT, STR);
}

extern "C" void kernel_launch(void* const* d_in, const int* in_sizes, int n_in,
                              void* d_out, int out_size) {
    const float* x   = (const float*)d_in[0];
    const int*   ei  = (const int*)d_in[1];
    const int E = in_sizes[1] / 2;
    const int n = in_sizes[0] / 19;
    const int* src = ei;
    const int* dst = ei + E;

    const float* l0w1 = (const float*)d_in[2];
    const float* l0b1 = (const float*)d_in[3];
    const float* l0w2 = (const float*)d_in[4];
    const float* l0b2 = (const float*)d_in[5];
    const float* l1w1 = (const float*)d_in[6];
    const float* l1b1 = (const float*)d_in[7];
    const float* l1w2 = (const float*)d_in[8];
    const float* l1b2 = (const float*)d_in[9];
    const float* l2w1 = (const float*)d_in[10];
    const float* l2b1 = (const float*)d_in[11];
    const float* l2w2 = (const float*)d_in[12];
    const float* l2b2 = (const float*)d_in[13];
    const float* l3w1 = (const float*)d_in[14];
    const float* l3b1 = (const float*)d_in[15];
    const float* l3w2 = (const float*)d_in[16];
    const float* l3b2 = (const float*)d_in[17];
    const float* m_w  = (const float*)d_in[18];
    const float* m_b  = (const float*)d_in[19];
    const float* d_w1 = (const float*)d_in[20];
    const float* d_b1 = (const float*)d_in[21];
    const float* d_w2 = (const float*)d_in[22];
    const float* d_b2 = (const float*)d_in[23];

    void *pH, *pZ, *pT, *pX, *pW, *pVm, *pVd, *pSc, *pTd, *pRow, *pCnt, *pCur, *pPart, *pBsum, *pEsrc;
    cudaGetSymbolAddress(&pH, g_h16);
    cudaGetSymbolAddress(&pZ, g_z16);
    cudaGetSymbolAddress(&pT, g_t16);
    cudaGetSymbolAddress(&pX, g_x16);
    cudaGetSymbolAddress(&pW, g_w16);
    cudaGetSymbolAddress(&pVm, g_vm);
    cudaGetSymbolAddress(&pVd, g_vd);
    cudaGetSymbolAddress(&pSc, g_sc);
    cudaGetSymbolAddress(&pTd, g_td);
    cudaGetSymbolAddress(&pRow, g_rowp);
    cudaGetSymbolAddress(&pCnt, g_cnt);
    cudaGetSymbolAddress(&pCur, g_cur);
    cudaGetSymbolAddress(&pPart, g_part);
    cudaGetSymbolAddress(&pBsum, g_bsum);
    cudaGetSymbolAddress(&pEsrc, g_esrc);
    __half* h16 = (__half*)pH;
    __half* z16 = (__half*)pZ;
    __half* t16 = (__half*)pT;
    __half* x16 = (__half*)pX;
    __half* w16 = (__half*)pW;
    float* vm = (float*)pVm;
    float* vd = (float*)pVd;
    float* sc = (float*)pSc;
    float* td = (float*)pTd;
    int* rowp = (int*)pRow;
    int* cnt  = (int*)pCnt;
    int* cur  = (int*)pCur;
    int* part = (int*)pPart;
    int* bsum = (int*)pBsum;
    int* esrc = (int*)pEsrc;

    float* out = (float*)d_out;

    const int TB = 256;
    const int edgeBlocks = (E + TB - 1) / TB;
    const int nodeBlocks = (n + TB - 1) / TB;
    const int warpBlocks = (n * 32 + TB - 1) / TB;  // warp per node
    const int nb = (n + 255) / 256;

    // ---- independent precomputes ----
    f2h_k<<<(n * 19 + 255) / 256, 256>>>(x, x16, n * 19);
    precomp_k<<<1, 64>>>(l3w2, l3b2, m_w, m_b, d_w1, vm, vd, sc);
    launch_conv_w(l0w1, w16 + W0A_OFF, 19, 128, 40);
    launch_conv_w(l0w2, w16 + W0B_OFF, 128, 128, 136);
    launch_conv_w(l1w1, w16 + W1A_OFF, 128, 128, 136);
    launch_conv_w(l1w2, w16 + W1B_OFF, 128, 128, 136);
    launch_conv_w(l2w1, w16 + W2A_OFF, 128, 128, 136);
    launch_conv_w(l2w2, w16 + W2B_OFF, 128, 128, 136);
    launch_conv_w(l3w1, w16 + W3A_OFF, 128, 64, 136);

    // ---- CSR build ----
    cudaMemsetAsync(cnt, 0, (size_t)n * sizeof(int));
    count_k<<<(E / 4 + TB - 1) / TB, TB>>>(dst, cnt, E);
    block_scan_k<<<nb, 256>>>(cnt, part, bsum, n);
    scan_bsum_k<<<1, 256>>>(bsum, nb);
    finalize_rowp_k<<<nodeBlocks, TB>>>(part, bsum, rowp, cur, n);
    fill_k<<<edgeBlocks, TB>>>(src, dst, cur, esrc, E);

    // ---- layer 0 ----
    agg19h_k<<<warpBlocks, TB>>>(x16, rowp, esrc, z16, n);
    launch_gemm_h<19, 128, true>(z16, w16 + W0A_OFF, l0b1, t16, n);
    launch_gemm_h<128, 128, true>(t16, w16 + W0B_OFF, l0b2, h16, n);  // h0 fp16

    // ---- layer 1 ----
    agg128h_k<<<warpBlocks, TB>>>(h16, rowp, esrc, z16, n);
    launch_gemm_h<128, 128, true>(z16, w16 + W1A_OFF, l1b1, t16, n);
    launch_gemm_h<128, 128, true>(t16, w16 + W1B_OFF, l1b2, h16, n);  // h1 fp16

    // ---- layer 2 ----
    agg128h_k<<<warpBlocks, TB>>>(h16, rowp, esrc, z16, n);
    launch_gemm_h<128, 128, true>(z16, w16 + W2A_OFF, l2b1, t16, n);
    launch_gemm_h<128, 128, true>(t16, w16 + W2B_OFF, l2b2, z16, n);  // h2 fp16 (into z16)

    // ---- layer 3: y = h2 @ W1 (64-dim fp16), aggregate at 64, fused heads ----
    launch_gemm_h<128, 64, false>(z16, w16 + W3A_OFF, nullptr, h16, n); // y fp16
    agg64_heads_k<<<warpBlocks, TB>>>(h16, rowp, esrc, l3b1, vm, vd, sc,
                                      out + n, td, n);

    // ---- discriminator ----
    discrim_k<<<nodeBlocks, TB>>>(td, rowp, esrc, d_b1, d_w2, d_b2, out, n);
}

// round 16
// speedup vs baseline: 1.1363x; 1.0288x over previous
#include <cuda_runtime.h>
#include <cuda_fp16.h>
#include <cstdint>

#define NN 50000
#define NE 1600000

// Wt16 layout offsets (halfs): [col*STR + k], STR = KP+8
#define W0A_OFF 0                      // l0w1: 19->128,  KP=32,  STR=40,  128*40  = 5120
#define W0B_OFF 5120                   // l0w2: 128->128, STR=136, 128*136 = 17408
#define W1A_OFF (W0B_OFF + 17408)
#define W1B_OFF (W1A_OFF + 17408)
#define W2A_OFF (W1B_OFF + 17408)
#define W2B_OFF (W2A_OFF + 17408)
#define W3A_OFF (W2B_OFF + 17408)      // l3w1: 128->64, 64*136 = 8704
#define WT_TOTAL (W3A_OFF + 8704)

// ---------------- scratch (static device globals; no allocs allowed) ----------------
__device__ __half g_h16[NN * 128];   // gather source / y
__device__ __half g_z16[NN * 128];   // agg output / GEMM input
__device__ __half g_t16[NN * 128];   // MLP intermediate
__device__ __half g_x16[NN * 19];
__device__ __half g_w16[WT_TOTAL];   // pre-transposed fp16 weights
__device__ float  g_vm[64];
__device__ float  g_vd[64];
__device__ float  g_sc[2];
__device__ float  g_td[NN];
__device__ int    g_rowp[NN + 1];
__device__ int    g_cnt[NN];
__device__ int    g_cur[NN];
__device__ int    g_part[NN];
__device__ int    g_bsum[256];
__device__ int    g_esrc[NE];

// ---------------- consolidated setup kernel ----------------
// Segments (by global thread index): zero cnt | f2h | precomp | 7x weight transpose
__device__ __forceinline__ void conv_one(const float* __restrict__ W, __half* __restrict__ Wt,
                                         int IN, int OUT, int STR, int idx) {
    int col = idx / STR, kk = idx - col * STR;
    Wt[idx] = (kk < IN) ? __float2half_rn(W[kk * OUT + col]) : __ushort_as_half(0);
}

__global__ void setup_k(const float* __restrict__ x, __half* __restrict__ xh,
                        const float* __restrict__ w0a, const float* __restrict__ w0b,
                        const float* __restrict__ w1a, const float* __restrict__ w1b,
                        const float* __restrict__ w2a, const float* __restrict__ w2b,
                        const float* __restrict__ w3a, __half* __restrict__ wt,
                        const float* __restrict__ l3w2, const float* __restrict__ l3b2,
                        const float* __restrict__ m_w, const float* __restrict__ m_b,
                        const float* __restrict__ d_w1,
                        float* __restrict__ vm, float* __restrict__ vd, float* __restrict__ sc,
                        int* __restrict__ cnt, int n) {
    int i = blockIdx.x * blockDim.x + threadIdx.x;

    if (i < n) { cnt[i] = 0; return; }
    i -= n;

    if (i < n * 19) { xh[i] = __float2half_rn(x[i]); return; }
    i -= n * 19;

    if (i < 64) {
        float am = 0.0f, ad = 0.0f;
        for (int k = 0; k < 64; ++k) {
            float w = l3w2[i * 64 + k];
            am += w * m_w[k];
            ad += w * d_w1[k];
        }
        vm[i] = am;
        vd[i] = ad;
        if (i == 0) {
            float sm = m_b[0], sd = 0.0f;
            for (int k = 0; k < 64; ++k) {
                sm += l3b2[k] * m_w[k];
                sd += l3b2[k] * d_w1[k];
            }
            sc[0] = sm;
            sc[1] = sd;
        }
        return;
    }
    i -= 64;

    if (i < 5120)  { conv_one(w0a, wt + W0A_OFF, 19, 128, 40, i);  return; }
    i -= 5120;
    if (i < 17408) { conv_one(w0b, wt + W0B_OFF, 128, 128, 136, i); return; }
    i -= 17408;
    if (i < 17408) { conv_one(w1a, wt + W1A_OFF, 128, 128, 136, i); return; }
    i -= 17408;
    if (i < 17408) { conv_one(w1b, wt + W1B_OFF, 128, 128, 136, i); return; }
    i -= 17408;
    if (i < 17408) { conv_one(w2a, wt + W2A_OFF, 128, 128, 136, i); return; }
    i -= 17408;
    if (i < 17408) { conv_one(w2b, wt + W2B_OFF, 128, 128, 136, i); return; }
    i -= 17408;
    if (i < 8704)  { conv_one(w3a, wt + W3A_OFF, 128, 64, 136, i);  return; }
}

// ---------------- CSR build ----------------
__global__ void count_k(const int* __restrict__ dst, int* __restrict__ cnt, int E) {
    int base = (blockIdx.x * blockDim.x + threadIdx.x) * 4;
    if (base + 4 <= E) {
        int4 d = *(const int4*)(dst + base);
        atomicAdd(&cnt[d.x], 1);
        atomicAdd(&cnt[d.y], 1);
        atomicAdd(&cnt[d.z], 1);
        atomicAdd(&cnt[d.w], 1);
    } else {
        for (int e = base; e < E; ++e) atomicAdd(&cnt[dst[e]], 1);
    }
}

__global__ void block_scan_k(const int* __restrict__ cnt, int* __restrict__ part,
                             int* __restrict__ bsum, int n) {
    __shared__ int wsum[8];
    int t = threadIdx.x;
    int i = blockIdx.x * 256 + t;
    int v = (i < n) ? cnt[i] : 0;
    int lane = t & 31, w = t >> 5;
    int x = v;
#pragma unroll
    for (int o = 1; o < 32; o <<= 1) {
        int y = __shfl_up_sync(0xffffffffu, x, o);
        if (lane >= o) x += y;
    }
    if (lane == 31) wsum[w] = x;
    __syncthreads();
    if (w == 0) {
        int s = (lane < 8) ? wsum[lane] : 0;
#pragma unroll
        for (int o = 1; o < 8; o <<= 1) {
            int y = __shfl_up_sync(0xffffffffu, s, o);
            if (lane >= o) s += y;
        }
        if (lane < 8) wsum[lane] = s;
    }
    __syncthreads();
    if (w > 0) x += wsum[w - 1];
    if (i < n) part[i] = x;
    if (t == 255) bsum[blockIdx.x] = x;
}

__global__ void scan_bsum_k(int* __restrict__ bsum, int nb) {
    __shared__ int wsum[8];
    int t = threadIdx.x;
    int v = (t < nb) ? bsum[t] : 0;
    int lane = t & 31, w = t >> 5;
    int x = v;
#pragma unroll
    for (int o = 1; o < 32; o <<= 1) {
        int y = __shfl_up_sync(0xffffffffu, x, o);
        if (lane >= o) x += y;
    }
    if (lane == 31) wsum[w] = x;
    __syncthreads();
    if (w == 0) {
        int s = (lane < 8) ? wsum[lane] : 0;
#pragma unroll
        for (int o = 1; o < 8; o <<= 1) {
            int y = __shfl_up_sync(0xffffffffu, s, o);
            if (lane >= o) s += y;
        }
        if (lane < 8) wsum[lane] = s;
    }
    __syncthreads();
    if (w > 0) x += wsum[w - 1];
    if (t < nb) bsum[t] = x - v;   // exclusive
}

// rowp[i+1] = inclusive scan; cursor[i] = exclusive scan (= rowp[i]).
__global__ void finalize_rowp_k(const int* __restrict__ part, const int* __restrict__ bsum,
                                int* __restrict__ rowp, int* __restrict__ cursor, int n) {
    int i = blockIdx.x * blockDim.x + threadIdx.x;
    if (i == 0) rowp[0] = 0;
    if (i < n) {
        int incl = part[i] + bsum[i >> 8];
        rowp[i + 1] = incl;
        int v = (i & 255) ? (part[i - 1] + bsum[i >> 8]) : bsum[i >> 8];
        cursor[i] = v;
    }
}

__global__ void fill_k(const int* __restrict__ src, const int* __restrict__ dst,
                       int* __restrict__ cursor, int* __restrict__ esrc, int E) {
    int e = blockIdx.x * blockDim.x + threadIdx.x;
    if (e >= E) return;
    int d = dst[e];
    int p = atomicAdd(&cursor[d], 1);   // absolute slot
    esrc[p] = src[e];
}

// ---------------- aggregation kernels (R10-proven shapes) ----------------
__global__ void agg19h_k(const __half* __restrict__ xh, const int* __restrict__ rowp,
                         const int* __restrict__ esrc, __half* __restrict__ z, int n) {
    int w = (blockIdx.x * blockDim.x + threadIdx.x) >> 5;
    int lane = threadIdx.x & 31;
    if (w >= n || lane >= 19) return;
    float acc = __half2float(xh[w * 19 + lane]);
    int s = rowp[w], e = rowp[w + 1];
    int j = s;
    for (; j + 4 <= e; j += 4) {
        int s0 = esrc[j], s1 = esrc[j + 1], s2 = esrc[j + 2], s3 = esrc[j + 3];
        float a = __half2float(xh[s0 * 19 + lane]);
        float b = __half2float(xh[s1 * 19 + lane]);
        float c = __half2float(xh[s2 * 19 + lane]);
        float d = __half2float(xh[s3 * 19 + lane]);
        acc += a; acc += b; acc += c; acc += d;
    }
    for (; j < e; ++j) acc += __half2float(xh[esrc[j] * 19 + lane]);
    z[w * 19 + lane] = __float2half_rn(acc);
}

__device__ __forceinline__ void acc_h4(float4& acc, uint2 v) {
    float2 f0 = __half22float2(*(__half2*)&v.x);
    float2 f1 = __half22float2(*(__half2*)&v.y);
    acc.x += f0.x; acc.y += f0.y; acc.z += f1.x; acc.w += f1.y;
}

__global__ void agg128h_k(const __half* __restrict__ h, const int* __restrict__ rowp,
                          const int* __restrict__ esrc, __half* __restrict__ z, int n) {
    int w = (blockIdx.x * blockDim.x + threadIdx.x) >> 5;
    int lane = threadIdx.x & 31;
    if (w >= n) return;
    const uint2* h4 = (const uint2*)h;
    float4 acc = make_float4(0.f, 0.f, 0.f, 0.f);
    acc_h4(acc, h4[w * 32 + lane]);
    int s = rowp[w], e = rowp[w + 1];
    int j = s;
    for (; j + 8 <= e; j += 8) {
        int i0 = esrc[j],     i1 = esrc[j + 1], i2 = esrc[j + 2], i3 = esrc[j + 3];
        int i4 = esrc[j + 4], i5 = esrc[j + 5], i6 = esrc[j + 6], i7 = esrc[j + 7];
        uint2 v0 = h4[i0 * 32 + lane];
        uint2 v1 = h4[i1 * 32 + lane];
        uint2 v2 = h4[i2 * 32 + lane];
        uint2 v3 = h4[i3 * 32 + lane];
        uint2 v4 = h4[i4 * 32 + lane];
        uint2 v5 = h4[i5 * 32 + lane];
        uint2 v6 = h4[i6 * 32 + lane];
        uint2 v7 = h4[i7 * 32 + lane];
        acc_h4(acc, v0); acc_h4(acc, v1); acc_h4(acc, v2); acc_h4(acc, v3);
        acc_h4(acc, v4); acc_h4(acc, v5); acc_h4(acc, v6); acc_h4(acc, v7);
    }
    for (; j < e; ++j) acc_h4(acc, h4[esrc[j] * 32 + lane]);
    uint2 o;
    *(__half2*)&o.x = __floats2half2_rn(acc.x, acc.y);
    *(__half2*)&o.y = __floats2half2_rn(acc.z, acc.w);
    ((uint2*)z)[w * 32 + lane] = o;
}

__global__ void agg64_heads_k(const __half* __restrict__ y, const int* __restrict__ rowp,
                              const int* __restrict__ esrc, const float* __restrict__ bias,
                              const float* __restrict__ vm, const float* __restrict__ vd,
                              const float* __restrict__ sc,
                              float* __restrict__ mmse_out, float* __restrict__ td, int n) {
    int w = (blockIdx.x * blockDim.x + threadIdx.x) >> 5;
    int lane = threadIdx.x & 31;
    if (w >= n) return;
    const __half2* h2 = (const __half2*)y;  // 32 half2 per row
    float2 acc = __half22float2(h2[w * 32 + lane]);
    int s = rowp[w], e = rowp[w + 1];
    int j = s;
    for (; j + 8 <= e; j += 8) {
        int i0 = esrc[j],     i1 = esrc[j + 1], i2 = esrc[j + 2], i3 = esrc[j + 3];
        int i4 = esrc[j + 4], i5 = esrc[j + 5], i6 = esrc[j + 6], i7 = esrc[j + 7];
        float2 a = __half22float2(h2[i0 * 32 + lane]);
        float2 b = __half22float2(h2[i1 * 32 + lane]);
        float2 c = __half22float2(h2[i2 * 32 + lane]);
        float2 d = __half22float2(h2[i3 * 32 + lane]);
        float2 p = __half22float2(h2[i4 * 32 + lane]);
        float2 q = __half22float2(h2[i5 * 32 + lane]);
        float2 r = __half22float2(h2[i6 * 32 + lane]);
        float2 t = __half22float2(h2[i7 * 32 + lane]);
        acc.x += a.x; acc.y += a.y; acc.x += b.x; acc.y += b.y;
        acc.x += c.x; acc.y += c.y; acc.x += d.x; acc.y += d.y;
        acc.x += p.x; acc.y += p.y; acc.x += q.x; acc.y += q.y;
        acc.x += r.x; acc.y += r.y; acc.x += t.x; acc.y += t.y;
    }
    for (; j < e; ++j) {
        float2 f = __half22float2(h2[esrc[j] * 32 + lane]);
        acc.x += f.x; acc.y += f.y;
    }
    float ux = fmaxf(acc.x + bias[lane * 2], 0.0f);
    float uy = fmaxf(acc.y + bias[lane * 2 + 1], 0.0f);
    float dm = ux * vm[lane * 2] + uy * vm[lane * 2 + 1];
    float dd = ux * vd[lane * 2] + uy * vd[lane * 2 + 1];
#pragma unroll
    for (int o = 16; o; o >>= 1) {
        dm += __shfl_down_sync(0xffffffffu, dm, o);
        dd += __shfl_down_sync(0xffffffffu, dd, o);
    }
    if (lane == 0) {
        float m = dm + sc[0];
        mmse_out[w] = (m > 0.0f) ? m : 0.01f * m;
        td[w] = dd + sc[1];
    }
}

__global__ void discrim_k(const float* __restrict__ td, const int* __restrict__ rowp,
                          const int* __restrict__ esrc, const float* __restrict__ d_b1,
                          const float* __restrict__ d_w2, const float* __restrict__ d_b2,
                          float* __restrict__ out, int n) {
    int i = blockIdx.x * blockDim.x + threadIdx.x;
    if (i >= n) return;
    float acc = td[i];
    int s = rowp[i], e = rowp[i + 1];
    int j = s;
    for (; j + 4 <= e; j += 4) {
        float a = td[esrc[j]], b = td[esrc[j + 1]];
        float c = td[esrc[j + 2]], d = td[esrc[j + 3]];
        acc += a; acc += b; acc += c; acc += d;
    }
    for (; j < e; ++j) acc += td[esrc[j]];
    float u = acc + d_b1[0];
    u = fmaxf(u, 0.0f);
    out[i] = u * d_w2[0] + d_b2[0];
}

// ---------------- fp16 tensor-core GEMM (m16n8k16, ldmatrix, pre-staged weights) ------
__device__ __forceinline__ void ldsm4(uint32_t& r0, uint32_t& r1, uint32_t& r2, uint32_t& r3,
                                      uint32_t addr) {
    asm volatile("ldmatrix.sync.aligned.m8n8.x4.shared.b16 {%0,%1,%2,%3}, [%4];"
                 : "=r"(r0), "=r"(r1), "=r"(r2), "=r"(r3) : "r"(addr));
}

// C[n,OUT] = act(A[n,IN] @ Wt + bias); Wt pre-transposed fp16 in smem layout [col*STR+k].
template <int IN, int OUT, bool RELU>
__global__ void gemm_h_k(const __half* __restrict__ A, const __half* __restrict__ Wt,
                         const float* __restrict__ bias, __half* __restrict__ C, int n) {
    constexpr int KP = ((IN + 15) / 16) * 16;   // 32 / 128
    constexpr int STR = KP + 8;                 // padded k-stride in halfs
    constexpr int NT = OUT / 16;                // n8-tiles per warp
    constexpr int WSZ4 = OUT * STR / 8;         // W size in uint4

    extern __shared__ __half smh[];
    __half* Ws = smh;                           // [OUT][STR]
    __half* As = smh + OUT * STR;               // [128][STR]
    float* Bs = (float*)(smh + OUT * STR + 128 * STR);

    int tid = threadIdx.x;
    int row0 = blockIdx.x * 128;

    // stage W: straight uint4 copy (layout already matches)
    {
        const uint4* Wg = (const uint4*)Wt;
        uint4* Wsm = (uint4*)Ws;
        for (int i = tid; i < WSZ4; i += 256) Wsm[i] = Wg[i];
    }
    for (int i = tid; i < OUT; i += 256) Bs[i] = bias ? bias[i] : 0.0f;

    // stage A tile
    if (IN == 128) {
        const uint4* A4 = (const uint4*)A;
        for (int i = tid; i < 128 * 16; i += 256) {
            int r = i >> 4, kk = i & 15;
            int row = row0 + r;
            uint4 v = (row < n) ? A4[(size_t)row * 16 + kk] : make_uint4(0u, 0u, 0u, 0u);
            ((uint4*)(As + r * STR))[kk] = v;
        }
    } else {
        for (int i = tid; i < 128 * IN; i += 256) {
            int r = i / IN, k = i - r * IN;
            int row = row0 + r;
            As[r * STR + k] = (row < n) ? A[(size_t)row * IN + k] : __ushort_as_half(0);
        }
        for (int i = tid; i < 128 * (KP - IN); i += 256) {
            int r = i / (KP - IN), k = IN + i % (KP - IN);
            As[r * STR + k] = __ushort_as_half(0);
        }
    }
    __syncthreads();

    int w = tid >> 5, lane = tid & 31;
    int wm = w >> 1, wn = w & 1;                // 4 x 2 warp grid
    int g = lane >> 2, t4 = lane & 3;
    int rbase = wm * 32, cbase = wn * (OUT / 2);

    int q = lane & 7, set = lane >> 3;          // ldmatrix lane roles
    uint32_t aA0 = (uint32_t)__cvta_generic_to_shared(
        As + (rbase + (set & 1) * 8 + q) * STR + (set >> 1) * 8);
    uint32_t aA1 = aA0 + 16 * STR * 2;
    uint32_t aB[NT / 2];
#pragma unroll
    for (int p = 0; p < NT / 2; ++p)
        aB[p] = (uint32_t)__cvta_generic_to_shared(
            Ws + (cbase + p * 16 + (set >> 1) * 8 + q) * STR + (set & 1) * 8);

    float acc[2][NT][4];
#pragma unroll
    for (int mt = 0; mt < 2; ++mt)
#pragma unroll
        for (int nt = 0; nt < NT; ++nt)
#pragma unroll
            for (int z = 0; z < 4; ++z) acc[mt][nt][z] = 0.0f;

#pragma unroll
    for (int k0 = 0; k0 < KP; k0 += 16) {
        uint32_t a[2][4];
        ldsm4(a[0][0], a[0][1], a[0][2], a[0][3], aA0 + k0 * 2);
        ldsm4(a[1][0], a[1][1], a[1][2], a[1][3], aA1 + k0 * 2);
        uint32_t b[NT][2];
#pragma unroll
        for (int p = 0; p < NT / 2; ++p) {
            uint32_t r0, r1, r2, r3;
            ldsm4(r0, r1, r2, r3, aB[p] + k0 * 2);
            b[2 * p][0] = r0; b[2 * p][1] = r1;
            b[2 * p + 1][0] = r2; b[2 * p + 1][1] = r3;
        }
#pragma unroll
        for (int mt = 0; mt < 2; ++mt)
#pragma unroll
            for (int nt = 0; nt < NT; ++nt) {
                asm volatile(
                    "mma.sync.aligned.m16n8k16.row.col.f32.f16.f16.f32 "
                    "{%0,%1,%2,%3}, {%4,%5,%6,%7}, {%8,%9}, {%0,%1,%2,%3};\n"
                    : "+f"(acc[mt][nt][0]), "+f"(acc[mt][nt][1]),
                      "+f"(acc[mt][nt][2]), "+f"(acc[mt][nt][3])
                    : "r"(a[mt][0]), "r"(a[mt][1]), "r"(a[mt][2]), "r"(a[mt][3]),
                      "r"(b[nt][0]), "r"(b[nt][1]));
            }
    }

    // epilogue: bias + optional relu -> fp16
#pragma unroll
    for (int mt = 0; mt < 2; ++mt) {
        int r1 = row0 + rbase + mt * 16 + g;
#pragma unroll
        for (int nt = 0; nt < NT; ++nt) {
            int col = cbase + nt * 8 + t4 * 2;
            float b0 = Bs[col], b1 = Bs[col + 1];
            if (r1 < n) {
                float v0 = acc[mt][nt][0] + b0;
                float v1 = acc[mt][nt][1] + b1;
                if (RELU) { v0 = fmaxf(v0, 0.0f); v1 = fmaxf(v1, 0.0f); }
                *(__half2*)(C + (size_t)r1 * OUT + col) = __floats2half2_rn(v0, v1);
            }
            if (r1 + 8 < n) {
                float v2 = acc[mt][nt][2] + b0;
                float v3 = acc[mt][nt][3] + b1;
                if (RELU) { v2 = fmaxf(v2, 0.0f); v3 = fmaxf(v3, 0.0f); }
                *(__half2*)(C + (size_t)(r1 + 8) * OUT + col) = __floats2half2_rn(v2, v3);
            }
        }
    }
}

// ---------------- host ----------------
template <int IN, int OUT, bool RELU>
static void launch_gemm_h(const __half* A, const __half* Wt, const float* bias,
                          __half* C, int n) {
    constexpr int KP = ((IN + 15) / 16) * 16;
    constexpr int STR = KP + 8;
    size_t smb = (size_t)(OUT * STR + 128 * STR) * sizeof(__half) + OUT * sizeof(float);
    cudaFuncSetAttribute(gemm_h_k<IN, OUT, RELU>,
                         cudaFuncAttributeMaxDynamicSharedMemorySize, (int)smb);
    gemm_h_k<IN, OUT, RELU><<<(n + 127) / 128, 256, smb>>>(A, Wt, bias, C, n);
}

extern "C" void kernel_launch(void* const* d_in, const int* in_sizes, int n_in,
                              void* d_out, int out_size) {
    const float* x   = (const float*)d_in[0];
    const int*   ei  = (const int*)d_in[1];
    const int E = in_sizes[1] / 2;
    const int n = in_sizes[0] / 19;
    const int* src = ei;
    const int* dst = ei + E;

    const float* l0w1 = (const float*)d_in[2];
    const float* l0b1 = (const float*)d_in[3];
    const float* l0w2 = (const float*)d_in[4];
    const float* l0b2 = (const float*)d_in[5];
    const float* l1w1 = (const float*)d_in[6];
    const float* l1b1 = (const float*)d_in[7];
    const float* l1w2 = (const float*)d_in[8];
    const float* l1b2 = (const float*)d_in[9];
    const float* l2w1 = (const float*)d_in[10];
    const float* l2b1 = (const float*)d_in[11];
    const float* l2w2 = (const float*)d_in[12];
    const float* l2b2 = (const float*)d_in[13];
    const float* l3w1 = (const float*)d_in[14];
    const float* l3b1 = (const float*)d_in[15];
    const float* l3w2 = (const float*)d_in[16];
    const float* l3b2 = (const float*)d_in[17];
    const float* m_w  = (const float*)d_in[18];
    const float* m_b  = (const float*)d_in[19];
    const float* d_w1 = (const float*)d_in[20];
    const float* d_b1 = (const float*)d_in[21];
    const float* d_w2 = (const float*)d_in[22];
    const float* d_b2 = (const float*)d_in[23];

    void *pH, *pZ, *pT, *pX, *pW, *pVm, *pVd, *pSc, *pTd, *pRow, *pCnt, *pCur, *pPart, *pBsum, *pEsrc;
    cudaGetSymbolAddress(&pH, g_h16);
    cudaGetSymbolAddress(&pZ, g_z16);
    cudaGetSymbolAddress(&pT, g_t16);
    cudaGetSymbolAddress(&pX, g_x16);
    cudaGetSymbolAddress(&pW, g_w16);
    cudaGetSymbolAddress(&pVm, g_vm);
    cudaGetSymbolAddress(&pVd, g_vd);
    cudaGetSymbolAddress(&pSc, g_sc);
    cudaGetSymbolAddress(&pTd, g_td);
    cudaGetSymbolAddress(&pRow, g_rowp);
    cudaGetSymbolAddress(&pCnt, g_cnt);
    cudaGetSymbolAddress(&pCur, g_cur);
    cudaGetSymbolAddress(&pPart, g_part);
    cudaGetSymbolAddress(&pBsum, g_bsum);
    cudaGetSymbolAddress(&pEsrc, g_esrc);
    __half* h16 = (__half*)pH;
    __half* z16 = (__half*)pZ;
    __half* t16 = (__half*)pT;
    __half* x16 = (__half*)pX;
    __half* w16 = (__half*)pW;
    float* vm = (float*)pVm;
    float* vd = (float*)pVd;
    float* sc = (float*)pSc;
    float* td = (float*)pTd;
    int* rowp = (int*)pRow;
    int* cnt  = (int*)pCnt;
    int* cur  = (int*)pCur;
    int* part = (int*)pPart;
    int* bsum = (int*)pBsum;
    int* esrc = (int*)pEsrc;

    float* out = (float*)d_out;

    const int TB = 256;
    const int edgeBlocks = (E + TB - 1) / TB;
    const int nodeBlocks = (n + TB - 1) / TB;
    const int warpBlocks = (n * 32 + TB - 1) / TB;  // warp per node
    const int nb = (n + 255) / 256;

    // ---- consolidated setup: zero cnt + f2h + precomp + 7 weight transposes ----
    {
        int totalItems = n + n * 19 + 64 + 5120 + 5 * 17408 + 8704;
        setup_k<<<(totalItems + TB - 1) / TB, TB>>>(
            x, x16,
            l0w1, l0w2, l1w1, l1w2, l2w1, l2w2, l3w1, w16,
            l3w2, l3b2, m_w, m_b, d_w1,
            vm, vd, sc, cnt, n);
    }

    // ---- CSR build ----
    count_k<<<(E / 4 + TB - 1) / TB, TB>>>(dst, cnt, E);
    block_scan_k<<<nb, 256>>>(cnt, part, bsum, n);
    scan_bsum_k<<<1, 256>>>(bsum, nb);
    finalize_rowp_k<<<nodeBlocks, TB>>>(part, bsum, rowp, cur, n);
    fill_k<<<edgeBlocks, TB>>>(src, dst, cur, esrc, E);

    // ---- layer 0 ----
    agg19h_k<<<warpBlocks, TB>>>(x16, rowp, esrc, z16, n);
    launch_gemm_h<19, 128, true>(z16, w16 + W0A_OFF, l0b1, t16, n);
    launch_gemm_h<128, 128, true>(t16, w16 + W0B_OFF, l0b2, h16, n);  // h0 fp16

    // ---- layer 1 ----
    agg128h_k<<<warpBlocks, TB>>>(h16, rowp, esrc, z16, n);
    launch_gemm_h<128, 128, true>(z16, w16 + W1A_OFF, l1b1, t16, n);
    launch_gemm_h<128, 128, true>(t16, w16 + W1B_OFF, l1b2, h16, n);  // h1 fp16

    // ---- layer 2 ----
    agg128h_k<<<warpBlocks, TB>>>(h16, rowp, esrc, z16, n);
    launch_gemm_h<128, 128, true>(z16, w16 + W2A_OFF, l2b1, t16, n);
    launch_gemm_h<128, 128, true>(t16, w16 + W2B_OFF, l2b2, z16, n);  // h2 fp16 (into z16)

    // ---- layer 3: y = h2 @ W1 (64-dim fp16), aggregate at 64, fused heads ----
    launch_gemm_h<128, 64, false>(z16, w16 + W3A_OFF, nullptr, h16, n); // y fp16
    agg64_heads_k<<<warpBlocks, TB>>>(h16, rowp, esrc, l3b1, vm, vd, sc,
                                      out + n, td, n);

    // ---- discriminator ----
    discrim_k<<<nodeBlocks, TB>>>(td, rowp, esrc, d_b1, d_w2, d_b2, out, n);
}

// round 17
// speedup vs baseline: 1.2584x; 1.1074x over previous
#include <cuda_runtime.h>
#include <cuda_fp16.h>
#include <cstdint>

#define NN 50000
#define NE 1600000

// Wt16 layout offsets (halfs): [col*STR + k], STR = KP+8
#define W0A_OFF 0                      // l0w1: 19->128,  KP=32,  STR=40,  128*40  = 5120
#define W0B_OFF 5120                   // l0w2: 128->128, STR=136, 128*136 = 17408
#define W1A_OFF (W0B_OFF + 17408)
#define W1B_OFF (W1A_OFF + 17408)
#define W2A_OFF (W1B_OFF + 17408)
#define W2B_OFF (W2A_OFF + 17408)
#define W3A_OFF (W2B_OFF + 17408)      // l3w1: 128->64, 64*136 = 8704
#define WT_TOTAL (W3A_OFF + 8704)

// ---------------- scratch (static device globals; no allocs allowed) ----------------
__device__ __half g_h16[NN * 128];   // gather source / y
__device__ __half g_z16[NN * 128];   // agg output / GEMM input
__device__ __half g_t16[NN * 128];   // layer-2 output
__device__ __half g_x16[NN * 19];
__device__ __half g_w16[WT_TOTAL];   // pre-transposed fp16 weights
__device__ float  g_vm[64];
__device__ float  g_vd[64];
__device__ float  g_sc[2];
__device__ float  g_td[NN];
__device__ int    g_rowp[NN + 1];
__device__ int    g_cnt[NN];
__device__ int    g_cur[NN];
__device__ int    g_part[NN];
__device__ int    g_bsum[256];
__device__ int    g_esrc[NE];

// ---------------- consolidated setup kernel ----------------
__device__ __forceinline__ void conv_one(const float* __restrict__ W, __half* __restrict__ Wt,
                                         int IN, int OUT, int STR, int idx) {
    int col = idx / STR, kk = idx - col * STR;
    Wt[idx] = (kk < IN) ? __float2half_rn(W[kk * OUT + col]) : __ushort_as_half(0);
}

__global__ void setup_k(const float* __restrict__ x, __half* __restrict__ xh,
                        const float* __restrict__ w0a, const float* __restrict__ w0b,
                        const float* __restrict__ w1a, const float* __restrict__ w1b,
                        const float* __restrict__ w2a, const float* __restrict__ w2b,
                        const float* __restrict__ w3a, __half* __restrict__ wt,
                        const float* __restrict__ l3w2, const float* __restrict__ l3b2,
                        const float* __restrict__ m_w, const float* __restrict__ m_b,
                        const float* __restrict__ d_w1,
                        float* __restrict__ vm, float* __restrict__ vd, float* __restrict__ sc,
                        int* __restrict__ cnt, int n) {
    int i = blockIdx.x * blockDim.x + threadIdx.x;

    if (i < n) { cnt[i] = 0; return; }
    i -= n;

    if (i < n * 19) { xh[i] = __float2half_rn(x[i]); return; }
    i -= n * 19;

    if (i < 64) {
        float am = 0.0f, ad = 0.0f;
        for (int k = 0; k < 64; ++k) {
            float w = l3w2[i * 64 + k];
            am += w * m_w[k];
            ad += w * d_w1[k];
        }
        vm[i] = am;
        vd[i] = ad;
        if (i == 0) {
            float sm = m_b[0], sd = 0.0f;
            for (int k = 0; k < 64; ++k) {
                sm += l3b2[k] * m_w[k];
                sd += l3b2[k] * d_w1[k];
            }
            sc[0] = sm;
            sc[1] = sd;
        }
        return;
    }
    i -= 64;

    if (i < 5120)  { conv_one(w0a, wt + W0A_OFF, 19, 128, 40, i);  return; }
    i -= 5120;
    if (i < 17408) { conv_one(w0b, wt + W0B_OFF, 128, 128, 136, i); return; }
    i -= 17408;
    if (i < 17408) { conv_one(w1a, wt + W1A_OFF, 128, 128, 136, i); return; }
    i -= 17408;
    if (i < 17408) { conv_one(w1b, wt + W1B_OFF, 128, 128, 136, i); return; }
    i -= 17408;
    if (i < 17408) { conv_one(w2a, wt + W2A_OFF, 128, 128, 136, i); return; }
    i -= 17408;
    if (i < 17408) { conv_one(w2b, wt + W2B_OFF, 128, 128, 136, i); return; }
    i -= 17408;
    if (i < 8704)  { conv_one(w3a, wt + W3A_OFF, 128, 64, 136, i);  return; }
}

// ---------------- CSR build ----------------
__global__ void count_k(const int* __restrict__ dst, int* __restrict__ cnt, int E) {
    int base = (blockIdx.x * blockDim.x + threadIdx.x) * 4;
    if (base + 4 <= E) {
        int4 d = *(const int4*)(dst + base);
        atomicAdd(&cnt[d.x], 1);
        atomicAdd(&cnt[d.y], 1);
        atomicAdd(&cnt[d.z], 1);
        atomicAdd(&cnt[d.w], 1);
    } else {
        for (int e = base; e < E; ++e) atomicAdd(&cnt[dst[e]], 1);
    }
}

__global__ void block_scan_k(const int* __restrict__ cnt, int* __restrict__ part,
                             int* __restrict__ bsum, int n) {
    __shared__ int wsum[8];
    int t = threadIdx.x;
    int i = blockIdx.x * 256 + t;
    int v = (i < n) ? cnt[i] : 0;
    int lane = t & 31, w = t >> 5;
    int x = v;
#pragma unroll
    for (int o = 1; o < 32; o <<= 1) {
        int y = __shfl_up_sync(0xffffffffu, x, o);
        if (lane >= o) x += y;
    }
    if (lane == 31) wsum[w] = x;
    __syncthreads();
    if (w == 0) {
        int s = (lane < 8) ? wsum[lane] : 0;
#pragma unroll
        for (int o = 1; o < 8; o <<= 1) {
            int y = __shfl_up_sync(0xffffffffu, s, o);
            if (lane >= o) s += y;
        }
        if (lane < 8) wsum[lane] = s;
    }
    __syncthreads();
    if (w > 0) x += wsum[w - 1];
    if (i < n) part[i] = x;
    if (t == 255) bsum[blockIdx.x] = x;
}

__global__ void scan_bsum_k(int* __restrict__ bsum, int nb) {
    __shared__ int wsum[8];
    int t = threadIdx.x;
    int v = (t < nb) ? bsum[t] : 0;
    int lane = t & 31, w = t >> 5;
    int x = v;
#pragma unroll
    for (int o = 1; o < 32; o <<= 1) {
        int y = __shfl_up_sync(0xffffffffu, x, o);
        if (lane >= o) x += y;
    }
    if (lane == 31) wsum[w] = x;
    __syncthreads();
    if (w == 0) {
        int s = (lane < 8) ? wsum[lane] : 0;
#pragma unroll
        for (int o = 1; o < 8; o <<= 1) {
            int y = __shfl_up_sync(0xffffffffu, s, o);
            if (lane >= o) s += y;
        }
        if (lane < 8) wsum[lane] = s;
    }
    __syncthreads();
    if (w > 0) x += wsum[w - 1];
    if (t < nb) bsum[t] = x - v;   // exclusive
}

__global__ void finalize_rowp_k(const int* __restrict__ part, const int* __restrict__ bsum,
                                int* __restrict__ rowp, int* __restrict__ cursor, int n) {
    int i = blockIdx.x * blockDim.x + threadIdx.x;
    if (i == 0) rowp[0] = 0;
    if (i < n) {
        int incl = part[i] + bsum[i >> 8];
        rowp[i + 1] = incl;
        int v = (i & 255) ? (part[i - 1] + bsum[i >> 8]) : bsum[i >> 8];
        cursor[i] = v;
    }
}

__global__ void fill_k(const int* __restrict__ src, const int* __restrict__ dst,
                       int* __restrict__ cursor, int* __restrict__ esrc, int E) {
    int e = blockIdx.x * blockDim.x + threadIdx.x;
    if (e >= E) return;
    int d = dst[e];
    int p = atomicAdd(&cursor[d], 1);   // absolute slot
    esrc[p] = src[e];
}

// ---------------- aggregation kernels (R10-proven shapes) ----------------
__global__ void agg19h_k(const __half* __restrict__ xh, const int* __restrict__ rowp,
                         const int* __restrict__ esrc, __half* __restrict__ z, int n) {
    int w = (blockIdx.x * blockDim.x + threadIdx.x) >> 5;
    int lane = threadIdx.x & 31;
    if (w >= n || lane >= 19) return;
    float acc = __half2float(xh[w * 19 + lane]);
    int s = rowp[w], e = rowp[w + 1];
    int j = s;
    for (; j + 4 <= e; j += 4) {
        int s0 = esrc[j], s1 = esrc[j + 1], s2 = esrc[j + 2], s3 = esrc[j + 3];
        float a = __half2float(xh[s0 * 19 + lane]);
        float b = __half2float(xh[s1 * 19 + lane]);
        float c = __half2float(xh[s2 * 19 + lane]);
        float d = __half2float(xh[s3 * 19 + lane]);
        acc += a; acc += b; acc += c; acc += d;
    }
    for (; j < e; ++j) acc += __half2float(xh[esrc[j] * 19 + lane]);
    z[w * 19 + lane] = __float2half_rn(acc);
}

__device__ __forceinline__ void acc_h4(float4& acc, uint2 v) {
    float2 f0 = __half22float2(*(__half2*)&v.x);
    float2 f1 = __half22float2(*(__half2*)&v.y);
    acc.x += f0.x; acc.y += f0.y; acc.z += f1.x; acc.w += f1.y;
}

__global__ void agg128h_k(const __half* __restrict__ h, const int* __restrict__ rowp,
                          const int* __restrict__ esrc, __half* __restrict__ z, int n) {
    int w = (blockIdx.x * blockDim.x + threadIdx.x) >> 5;
    int lane = threadIdx.x & 31;
    if (w >= n) return;
    const uint2* h4 = (const uint2*)h;
    float4 acc = make_float4(0.f, 0.f, 0.f, 0.f);
    acc_h4(acc, h4[w * 32 + lane]);
    int s = rowp[w], e = rowp[w + 1];
    int j = s;
    for (; j + 8 <= e; j += 8) {
        int i0 = esrc[j],     i1 = esrc[j + 1], i2 = esrc[j + 2], i3 = esrc[j + 3];
        int i4 = esrc[j + 4], i5 = esrc[j + 5], i6 = esrc[j + 6], i7 = esrc[j + 7];
        uint2 v0 = h4[i0 * 32 + lane];
        uint2 v1 = h4[i1 * 32 + lane];
        uint2 v2 = h4[i2 * 32 + lane];
        uint2 v3 = h4[i3 * 32 + lane];
        uint2 v4 = h4[i4 * 32 + lane];
        uint2 v5 = h4[i5 * 32 + lane];
        uint2 v6 = h4[i6 * 32 + lane];
        uint2 v7 = h4[i7 * 32 + lane];
        acc_h4(acc, v0); acc_h4(acc, v1); acc_h4(acc, v2); acc_h4(acc, v3);
        acc_h4(acc, v4); acc_h4(acc, v5); acc_h4(acc, v6); acc_h4(acc, v7);
    }
    for (; j < e; ++j) acc_h4(acc, h4[esrc[j] * 32 + lane]);
    uint2 o;
    *(__half2*)&o.x = __floats2half2_rn(acc.x, acc.y);
    *(__half2*)&o.y = __floats2half2_rn(acc.z, acc.w);
    ((uint2*)z)[w * 32 + lane] = o;
}

__global__ void agg64_heads_k(const __half* __restrict__ y, const int* __restrict__ rowp,
                              const int* __restrict__ esrc, const float* __restrict__ bias,
                              const float* __restrict__ vm, const float* __restrict__ vd,
                              const float* __restrict__ sc,
                              float* __restrict__ mmse_out, float* __restrict__ td, int n) {
    int w = (blockIdx.x * blockDim.x + threadIdx.x) >> 5;
    int lane = threadIdx.x & 31;
    if (w >= n) return;
    const __half2* h2 = (const __half2*)y;  // 32 half2 per row
    float2 acc = __half22float2(h2[w * 32 + lane]);
    int s = rowp[w], e = rowp[w + 1];
    int j = s;
    for (; j + 8 <= e; j += 8) {
        int i0 = esrc[j],     i1 = esrc[j + 1], i2 = esrc[j + 2], i3 = esrc[j + 3];
        int i4 = esrc[j + 4], i5 = esrc[j + 5], i6 = esrc[j + 6], i7 = esrc[j + 7];
        float2 a = __half22float2(h2[i0 * 32 + lane]);
        float2 b = __half22float2(h2[i1 * 32 + lane]);
        float2 c = __half22float2(h2[i2 * 32 + lane]);
        float2 d = __half22float2(h2[i3 * 32 + lane]);
        float2 p = __half22float2(h2[i4 * 32 + lane]);
        float2 q = __half22float2(h2[i5 * 32 + lane]);
        float2 r = __half22float2(h2[i6 * 32 + lane]);
        float2 t = __half22float2(h2[i7 * 32 + lane]);
        acc.x += a.x; acc.y += a.y; acc.x += b.x; acc.y += b.y;
        acc.x += c.x; acc.y += c.y; acc.x += d.x; acc.y += d.y;
        acc.x += p.x; acc.y += p.y; acc.x += q.x; acc.y += q.y;
        acc.x += r.x; acc.y += r.y; acc.x += t.x; acc.y += t.y;
    }
    for (; j < e; ++j) {
        float2 f = __half22float2(h2[esrc[j] * 32 + lane]);
        acc.x += f.x; acc.y += f.y;
    }
    float ux = fmaxf(acc.x + bias[lane * 2], 0.0f);
    float uy = fmaxf(acc.y + bias[lane * 2 + 1], 0.0f);
    float dm = ux * vm[lane * 2] + uy * vm[lane * 2 + 1];
    float dd = ux * vd[lane * 2] + uy * vd[lane * 2 + 1];
#pragma unroll
    for (int o = 16; o; o >>= 1) {
        dm += __shfl_down_sync(0xffffffffu, dm, o);
        dd += __shfl_down_sync(0xffffffffu, dd, o);
    }
    if (lane == 0) {
        float m = dm + sc[0];
        mmse_out[w] = (m > 0.0f) ? m : 0.01f * m;
        td[w] = dd + sc[1];
    }
}

__global__ void discrim_k(const float* __restrict__ td, const int* __restrict__ rowp,
                          const int* __restrict__ esrc, const float* __restrict__ d_b1,
                          const float* __restrict__ d_w2, const float* __restrict__ d_b2,
                          float* __restrict__ out, int n) {
    int i = blockIdx.x * blockDim.x + threadIdx.x;
    if (i >= n) return;
    float acc = td[i];
    int s = rowp[i], e = rowp[i + 1];
    int j = s;
    for (; j + 4 <= e; j += 4) {
        float a = td[esrc[j]], b = td[esrc[j + 1]];
        float c = td[esrc[j + 2]], d = td[esrc[j + 3]];
        acc += a; acc += b; acc += c; acc += d;
    }
    for (; j < e; ++j) acc += td[esrc[j]];
    float u = acc + d_b1[0];
    u = fmaxf(u, 0.0f);
    out[i] = u * d_w2[0] + d_b2[0];
}

// ---------------- MMA helpers ----------------
__device__ __forceinline__ void ldsm4(uint32_t& r0, uint32_t& r1, uint32_t& r2, uint32_t& r3,
                                      uint32_t addr) {
    asm volatile("ldmatrix.sync.aligned.m8n8.x4.shared.b16 {%0,%1,%2,%3}, [%4];"
                 : "=r"(r0), "=r"(r1), "=r"(r2), "=r"(r3) : "r"(addr));
}

#define MMA16816(acc, a, b0v, b1v)                                               \
    asm volatile(                                                                \
        "mma.sync.aligned.m16n8k16.row.col.f32.f16.f16.f32 "                     \
        "{%0,%1,%2,%3}, {%4,%5,%6,%7}, {%8,%9}, {%0,%1,%2,%3};\n"                \
        : "+f"(acc[0]), "+f"(acc[1]), "+f"(acc[2]), "+f"(acc[3])                 \
        : "r"(a[0]), "r"(a[1]), "r"(a[2]), "r"(a[3]), "r"(b0v), "r"(b1v))

// One MMA phase: rows rbase..rbase+31 (2 x m16), 64 cols cbase..cbase+63 (NT=8).
template <int KP, int STRH>
__device__ __forceinline__ void mma_phase(const __half* __restrict__ Asrc,
                                          const __half* __restrict__ Wsrc,
                                          int rbase, int cbase, int lane,
                                          float (&acc)[2][8][4]) {
    int q = lane & 7, set = lane >> 3;
    uint32_t aA0 = (uint32_t)__cvta_generic_to_shared(
        Asrc + (rbase + (set & 1) * 8 + q) * STRH + (set >> 1) * 8);
    uint32_t aA1 = aA0 + 16 * STRH * 2;
    uint32_t aB[4];
#pragma unroll
    for (int p = 0; p < 4; ++p)
        aB[p] = (uint32_t)__cvta_generic_to_shared(
            Wsrc + (cbase + p * 16 + (set >> 1) * 8 + q) * STRH + (set & 1) * 8);

#pragma unroll
    for (int mt = 0; mt < 2; ++mt)
#pragma unroll
        for (int nt = 0; nt < 8; ++nt)
#pragma unroll
            for (int z = 0; z < 4; ++z) acc[mt][nt][z] = 0.0f;

#pragma unroll
    for (int k0 = 0; k0 < KP; k0 += 16) {
        uint32_t a[2][4];
        ldsm4(a[0][0], a[0][1], a[0][2], a[0][3], aA0 + k0 * 2);
        ldsm4(a[1][0], a[1][1], a[1][2], a[1][3], aA1 + k0 * 2);
        uint32_t b[8][2];
#pragma unroll
        for (int p = 0; p < 4; ++p) {
            uint32_t r0, r1, r2, r3;
            ldsm4(r0, r1, r2, r3, aB[p] + k0 * 2);
            b[2 * p][0] = r0; b[2 * p][1] = r1;
            b[2 * p + 1][0] = r2; b[2 * p + 1][1] = r3;
        }
#pragma unroll
        for (int mt = 0; mt < 2; ++mt)
#pragma unroll
            for (int nt = 0; nt < 8; ++nt)
                MMA16816(acc[mt][nt], a[mt], b[nt][0], b[nt][1]);
    }
}

// ---------------- fused MLP: C = relu( relu(A@W1+b1) @ W2 + b2 ), OUT=128 --------------
template <int IN>
__global__ void fused2_k(const __half* __restrict__ A,
                         const __half* __restrict__ Wt1, const float* __restrict__ B1g,
                         const __half* __restrict__ Wt2, const float* __restrict__ B2g,
                         __half* __restrict__ C, int n) {
    constexpr int KP1 = ((IN + 15) / 16) * 16;   // 32 or 128
    constexpr int STR1 = KP1 + 8;                // 40 or 136
    constexpr int STR2 = 136;
    constexpr int W1SZ = 128 * STR1;
    constexpr int W2SZ = 128 * STR2;
    constexpr bool SEP = (IN != 128);            // separate U buffer for layer 0

    extern __shared__ __half smh[];
    __half* Ws1 = smh;
    __half* Ws2 = smh + W1SZ;
    __half* As  = Ws2 + W2SZ;                    // [128][STR1]
    __half* Us  = SEP ? (As + 128 * STR1) : As;  // [128][STR2]
    float* Bs1 = (float*)(Us + 128 * STR2);
    float* Bs2 = Bs1 + 128;

    int tid = threadIdx.x;
    int row0 = blockIdx.x * 128;

    // stage both weight tiles (uint4 copies; layout matches)
    {
        const uint4* Wg1 = (const uint4*)Wt1;
        uint4* Wsm1 = (uint4*)Ws1;
        for (int i = tid; i < W1SZ / 8; i += 256) Wsm1[i] = Wg1[i];
        const uint4* Wg2 = (const uint4*)Wt2;
        uint4* Wsm2 = (uint4*)Ws2;
        for (int i = tid; i < W2SZ / 8; i += 256) Wsm2[i] = Wg2[i];
    }
    for (int i = tid; i < 128; i += 256) { Bs1[i] = B1g[i]; Bs2[i] = B2g[i]; }

    // stage A tile
    if (IN == 128) {
        const uint4* A4 = (const uint4*)A;
        for (int i = tid; i < 128 * 16; i += 256) {
            int r = i >> 4, kk = i & 15;
            int row = row0 + r;
            uint4 v = (row < n) ? A4[(size_t)row * 16 + kk] : make_uint4(0u, 0u, 0u, 0u);
            ((uint4*)(As + r * STR1))[kk] = v;
        }
    } else {
        for (int i = tid; i < 128 * IN; i += 256) {
            int r = i / IN, k = i - r * IN;
            int row = row0 + r;
            As[r * STR1 + k] = (row < n) ? A[(size_t)row * IN + k] : __ushort_as_half(0);
        }
        for (int i = tid; i < 128 * (KP1 - IN); i += 256) {
            int r = i / (KP1 - IN), k = IN + i % (KP1 - IN);
            As[r * STR1 + k] = __ushort_as_half(0);
        }
    }
    __syncthreads();

    int w = tid >> 5, lane = tid & 31;
    int wm = w >> 1, wn = w & 1;                 // 4 x 2 warp grid
    int g = lane >> 2, t4 = lane & 3;
    int rbase = wm * 32, cbase = wn * 64;

    float acc[2][8][4];

    // ---- phase 1: u = relu(A @ W1 + b1) ----
    mma_phase<KP1, STR1>(As, Ws1, rbase, cbase, lane, acc);
    __syncthreads();   // all ldsm reads of As complete before overwriting (shared case)

#pragma unroll
    for (int mt = 0; mt < 2; ++mt) {
        int r1 = rbase + mt * 16 + g, r2 = r1 + 8;
#pragma unroll
        for (int nt = 0; nt < 8; ++nt) {
            int col = cbase + nt * 8 + t4 * 2;
            float b0 = Bs1[col], b1 = Bs1[col + 1];
            *(__half2*)(Us + r1 * STR2 + col) =
                __floats2half2_rn(fmaxf(acc[mt][nt][0] + b0, 0.0f),
                                  fmaxf(acc[mt][nt][1] + b1, 0.0f));
            *(__half2*)(Us + r2 * STR2 + col) =
                __floats2half2_rn(fmaxf(acc[mt][nt][2] + b0, 0.0f),
                                  fmaxf(acc[mt][nt][3] + b1, 0.0f));
        }
    }
    __syncthreads();

    // ---- phase 2: h = relu(u @ W2 + b2) -> global fp16 ----
    mma_phase<128, STR2>(Us, Ws2, rbase, cbase, lane, acc);

#pragma unroll
    for (int mt = 0; mt < 2; ++mt) {
        int r1 = row0 + rbase + mt * 16 + g;
#pragma unroll
        for (int nt = 0; nt < 8; ++nt) {
            int col = cbase + nt * 8 + t4 * 2;
            float b0 = Bs2[col], b1 = Bs2[col + 1];
            if (r1 < n)
                *(__half2*)(C + (size_t)r1 * 128 + col) =
                    __floats2half2_rn(fmaxf(acc[mt][nt][0] + b0, 0.0f),
                                      fmaxf(acc[mt][nt][1] + b1, 0.0f));
            if (r1 + 8 < n)
                *(__half2*)(C + (size_t)(r1 + 8) * 128 + col) =
                    __floats2half2_rn(fmaxf(acc[mt][nt][2] + b0, 0.0f),
                                      fmaxf(acc[mt][nt][3] + b1, 0.0f));
        }
    }
}

// ---------------- single GEMM for layer-3 projection: y = A @ W3 (128->64, no bias) ----
__global__ void gemm64_k(const __half* __restrict__ A, const __half* __restrict__ Wt,
                         __half* __restrict__ C, int n) {
    constexpr int STR = 136;
    constexpr int WSZ4 = 64 * STR / 8;

    extern __shared__ __half smh[];
    __half* Ws = smh;                            // [64][STR]
    __half* As = smh + 64 * STR;                 // [128][STR]

    int tid = threadIdx.x;
    int row0 = blockIdx.x * 128;

    {
        const uint4* Wg = (const uint4*)Wt;
        uint4* Wsm = (uint4*)Ws;
        for (int i = tid; i < WSZ4; i += 256) Wsm[i] = Wg[i];
    }
    {
        const uint4* A4 = (const uint4*)A;
        for (int i = tid; i < 128 * 16; i += 256) {
            int r = i >> 4, kk = i & 15;
            int row = row0 + r;
            uint4 v = (row < n) ? A4[(size_t)row * 16 + kk] : make_uint4(0u, 0u, 0u, 0u);
            ((uint4*)(As + r * STR))[kk] = v;
        }
    }
    __syncthreads();

    int w = tid >> 5, lane = tid & 31;
    int wm = w >> 1, wn = w & 1;                 // 4x2: 32 rows x 32 cols per warp
    int g = lane >> 2, t4 = lane & 3;
    int rbase = wm * 32, cbase = wn * 32;

    int q = lane & 7, set = lane >> 3;
    uint32_t aA0 = (uint32_t)__cvta_generic_to_shared(
        As + (rbase + (set & 1) * 8 + q) * STR + (set >> 1) * 8);
    uint32_t aA1 = aA0 + 16 * STR * 2;
    uint32_t aB[2];
#pragma unroll
    for (int p = 0; p < 2; ++p)
        aB[p] = (uint32_t)__cvta_generic_to_shared(
            Ws + (cbase + p * 16 + (set >> 1) * 8 + q) * STR + (set & 1) * 8);

    float acc[2][4][4];
#pragma unroll
    for (int mt = 0; mt < 2; ++mt)
#pragma unroll
        for (int nt = 0; nt < 4; ++nt)
#pragma unroll
            for (int z = 0; z < 4; ++z) acc[mt][nt][z] = 0.0f;

#pragma unroll
    for (int k0 = 0; k0 < 128; k0 += 16) {
        uint32_t a[2][4];
        ldsm4(a[0][0], a[0][1], a[0][2], a[0][3], aA0 + k0 * 2);
        ldsm4(a[1][0], a[1][1], a[1][2], a[1][3], aA1 + k0 * 2);
        uint32_t b[4][2];
#pragma unroll
        for (int p = 0; p < 2; ++p) {
            uint32_t r0, r1, r2, r3;
            ldsm4(r0, r1, r2, r3, aB[p] + k0 * 2);
            b[2 * p][0] = r0; b[2 * p][1] = r1;
            b[2 * p + 1][0] = r2; b[2 * p + 1][1] = r3;
        }
#pragma unroll
        for (int mt = 0; mt < 2; ++mt)
#pragma unroll
            for (int nt = 0; nt < 4; ++nt)
                MMA16816(acc[mt][nt], a[mt], b[nt][0], b[nt][1]);
    }

#pragma unroll
    for (int mt = 0; mt < 2; ++mt) {
        int r1 = row0 + rbase + mt * 16 + g;
#pragma unroll
        for (int nt = 0; nt < 4; ++nt) {
            int col = cbase + nt * 8 + t4 * 2;
            if (r1 < n)
                *(__half2*)(C + (size_t)r1 * 64 + col) =
                    __floats2half2_rn(acc[mt][nt][0], acc[mt][nt][1]);
            if (r1 + 8 < n)
                *(__half2*)(C + (size_t)(r1 + 8) * 64 + col) =
                    __floats2half2_rn(acc[mt][nt][2], acc[mt][nt][3]);
        }
    }
}

// ---------------- host ----------------
extern "C" void kernel_launch(void* const* d_in, const int* in_sizes, int n_in,
                              void* d_out, int out_size) {
    const float* x   = (const float*)d_in[0];
    const int*   ei  = (const int*)d_in[1];
    const int E = in_sizes[1] / 2;
    const int n = in_sizes[0] / 19;
    const int* src = ei;
    const int* dst = ei + E;

    const float* l0w1 = (const float*)d_in[2];
    const float* l0b1 = (const float*)d_in[3];
    const float* l0w2 = (const float*)d_in[4];
    const float* l0b2 = (const float*)d_in[5];
    const float* l1w1 = (const float*)d_in[6];
    const float* l1b1 = (const float*)d_in[7];
    const float* l1w2 = (const float*)d_in[8];
    const float* l1b2 = (const float*)d_in[9];
    const float* l2w1 = (const float*)d_in[10];
    const float* l2b1 = (const float*)d_in[11];
    const float* l2w2 = (const float*)d_in[12];
    const float* l2b2 = (const float*)d_in[13];
    const float* l3w1 = (const float*)d_in[14];
    const float* l3b1 = (const float*)d_in[15];
    const float* l3w2 = (const float*)d_in[16];
    const float* l3b2 = (const float*)d_in[17];
    const float* m_w  = (const float*)d_in[18];
    const float* m_b  = (const float*)d_in[19];
    const float* d_w1 = (const float*)d_in[20];
    const float* d_b1 = (const float*)d_in[21];
    const float* d_w2 = (const float*)d_in[22];
    const float* d_b2 = (const float*)d_in[23];

    void *pH, *pZ, *pT, *pX, *pW, *pVm, *pVd, *pSc, *pTd, *pRow, *pCnt, *pCur, *pPart, *pBsum, *pEsrc;
    cudaGetSymbolAddress(&pH, g_h16);
    cudaGetSymbolAddress(&pZ, g_z16);
    cudaGetSymbolAddress(&pT, g_t16);
    cudaGetSymbolAddress(&pX, g_x16);
    cudaGetSymbolAddress(&pW, g_w16);
    cudaGetSymbolAddress(&pVm, g_vm);
    cudaGetSymbolAddress(&pVd, g_vd);
    cudaGetSymbolAddress(&pSc, g_sc);
    cudaGetSymbolAddress(&pTd, g_td);
    cudaGetSymbolAddress(&pRow, g_rowp);
    cudaGetSymbolAddress(&pCnt, g_cnt);
    cudaGetSymbolAddress(&pCur, g_cur);
    cudaGetSymbolAddress(&pPart, g_part);
    cudaGetSymbolAddress(&pBsum, g_bsum);
    cudaGetSymbolAddress(&pEsrc, g_esrc);
    __half* h16 = (__half*)pH;
    __half* z16 = (__half*)pZ;
    __half* t16 = (__half*)pT;
    __half* x16 = (__half*)pX;
    __half* w16 = (__half*)pW;
    float* vm = (float*)pVm;
    float* vd = (float*)pVd;
    float* sc = (float*)pSc;
    float* td = (float*)pTd;
    int* rowp = (int*)pRow;
    int* cnt  = (int*)pCnt;
    int* cur  = (int*)pCur;
    int* part = (int*)pPart;
    int* bsum = (int*)pBsum;
    int* esrc = (int*)pEsrc;

    float* out = (float*)d_out;

    const int TB = 256;
    const int edgeBlocks = (E + TB - 1) / TB;
    const int nodeBlocks = (n + TB - 1) / TB;
    const int warpBlocks = (n * 32 + TB - 1) / TB;  // warp per node
    const int nb = (n + 255) / 256;
    const int gb = (n + 127) / 128;

    // smem sizes for fused kernels
    const size_t sm_f0 = (size_t)(128 * 40 + 128 * 136 + 128 * 40 + 128 * 136) * 2 + 256 * 4;
    const size_t sm_f1 = (size_t)(128 * 136 * 3) * 2 + 256 * 4;
    const size_t sm_g64 = (size_t)(64 * 136 + 128 * 136) * 2;
    cudaFuncSetAttribute(fused2_k<19>, cudaFuncAttributeMaxDynamicSharedMemorySize, (int)sm_f0);
    cudaFuncSetAttribute(fused2_k<128>, cudaFuncAttributeMaxDynamicSharedMemorySize, (int)sm_f1);
    cudaFuncSetAttribute(gemm64_k, cudaFuncAttributeMaxDynamicSharedMemorySize, (int)sm_g64);

    // ---- consolidated setup ----
    {
        int totalItems = n + n * 19 + 64 + 5120 + 5 * 17408 + 8704;
        setup_k<<<(totalItems + TB - 1) / TB, TB>>>(
            x, x16,
            l0w1, l0w2, l1w1, l1w2, l2w1, l2w2, l3w1, w16,
            l3w2, l3b2, m_w, m_b, d_w1,
            vm, vd, sc, cnt, n);
    }

    // ---- CSR build ----
    count_k<<<(E / 4 + TB - 1) / TB, TB>>>(dst, cnt, E);
    block_scan_k<<<nb, 256>>>(cnt, part, bsum, n);
    scan_bsum_k<<<1, 256>>>(bsum, nb);
    finalize_rowp_k<<<nodeBlocks, TB>>>(part, bsum, rowp, cur, n);
    fill_k<<<edgeBlocks, TB>>>(src, dst, cur, esrc, E);

    // ---- layer 0 (fused MLP) ----
    agg19h_k<<<warpBlocks, TB>>>(x16, rowp, esrc, z16, n);
    fused2_k<19><<<gb, 256, sm_f0>>>(z16, w16 + W0A_OFF, l0b1, w16 + W0B_OFF, l0b2, h16, n);

    // ---- layer 1 ----
    agg128h_k<<<warpBlocks, TB>>>(h16, rowp, esrc, z16, n);
    fused2_k<128><<<gb, 256, sm_f1>>>(z16, w16 + W1A_OFF, l1b1, w16 + W1B_OFF, l1b2, h16, n);

    // ---- layer 2 ----
    agg128h_k<<<warpBlocks, TB>>>(h16, rowp, esrc, z16, n);
    fused2_k<128><<<gb, 256, sm_f1>>>(z16, w16 + W2A_OFF, l2b1, w16 + W2B_OFF, l2b2, t16, n);

    // ---- layer 3: y = h2 @ W1 (64-dim fp16), aggregate at 64, fused heads ----
    gemm64_k<<<gb, 256, sm_g64>>>(t16, w16 + W3A_OFF, h16, n);  // y fp16
    agg64_heads_k<<<warpBlocks, TB>>>(h16, rowp, esrc, l3b1, vm, vd, sc,
                                      out + n, td, n);

    // ---- discriminator ----
    discrim_k<<<nodeBlocks, TB>>>(td, rowp, esrc, d_b1, d_w2, d_b2, out, n);
}